// round 7
// baseline (speedup 1.0000x reference)
#include <cuda_runtime.h>
#include <math.h>
#include <stdint.h>

// ---------------------------------------------------------------------------
// Problem shape (fixed)
// ---------------------------------------------------------------------------
constexpr int BATCH = 8;
constexpr int SEQ_T = 2048;
constexpr int D_MODEL = 1024;
constexpr int N_STATE = 1024;
constexpr int MROWS = BATCH * SEQ_T;      // 16384
constexpr int KDIM = 1024;
constexpr int CHUNK = 128;
constexpr int NCHUNK = SEQ_T / CHUNK;     // 16

// Scratch (no cudaMalloc allowed)
__device__ float g_bx[MROWS * N_STATE];                 // B_x -> h (rna'd by scan)
__device__ float g_xc[MROWS * D_MODEL];                 // rna(x)
__device__ float g_w1[N_STATE * D_MODEL];               // rna(B_w)
__device__ float g_w2[D_MODEL * N_STATE];               // rna(C_w)
__device__ float g_end[BATCH * NCHUNK * N_STATE];       // chunk-end states

__device__ __forceinline__ float sigmoidf_(float x) {
    return 1.0f / (1.0f + __expf(-x));
}
__device__ __forceinline__ uint32_t f2tf32(float x) {
    uint32_t r;
    asm("cvt.rna.tf32.f32 %0, %1;" : "=r"(r) : "f"(x));
    return r;
}
__device__ __forceinline__ uint32_t smem_u32(const void* p) {
    uint32_t a;
    asm("{ .reg .u64 t; cvta.to.shared.u64 t, %1; cvt.u32.u64 %0, t; }" : "=r"(a) : "l"(p));
    return a;
}

#define CP_ASYNC16(dst, src) \
    asm volatile("cp.async.cg.shared.global [%0], [%1], 16;" :: "r"(dst), "l"(src))
#define CP_COMMIT() asm volatile("cp.async.commit_group;" ::: "memory")
#define CP_WAIT1()  asm volatile("cp.async.wait_group 1;" ::: "memory")

#define LDSM_X4(r0, r1, r2, r3, addr) \
    asm volatile("ldmatrix.sync.aligned.m8n8.x4.shared.b16 {%0,%1,%2,%3}, [%4];" \
        : "=r"(r0), "=r"(r1), "=r"(r2), "=r"(r3) : "r"(addr))

// ---------------------------------------------------------------------------
// TF32 mma.sync GEMM: C[M,N=1024] = A[M,K]*B[N,K]^T + bias
// CTA tile 128x128x32, 4 warps (warp tile 64x64), 3-stage cp.async pipeline
// with ONE barrier per k-iter and fill-before-compute. SW128 smem + ldmatrix.
// ---------------------------------------------------------------------------
constexpr int BM = 128, BN = 128, BK = 32;
constexpr int A_BYTES = BM * 128;                 // 16 KB (32 floats/row = 128B)
constexpr int B_BYTES = BN * 128;                 // 16 KB
constexpr int STAGE_BYTES = A_BYTES + B_BYTES;    // 32 KB
constexpr int NSTAGE = 3;
constexpr int SMEM_GEMM_TOTAL = NSTAGE * STAGE_BYTES;  // 96 KB
constexpr int NITER = KDIM / BK;                  // 32

__global__ __launch_bounds__(128, 2) void gemm_tc_tf32(
    const float* __restrict__ A, const float* __restrict__ Bw,
    const float* __restrict__ bias, float* __restrict__ C)
{
    extern __shared__ char smem[];
    const uint32_t sb = smem_u32(smem);
    const int tid = threadIdx.x;
    const int wid = tid >> 5;
    const int lane = tid & 31;
    const int g = lane >> 2;          // 0..7
    const int t = lane & 3;           // 0..3
    const int mBase = blockIdx.y * BM;
    const int nBase = blockIdx.x * BN;
    const int warpM = (wid >> 1) * 64;
    const int warpN = (wid & 1) * 64;

    // ldmatrix lane roles
    const int j = lane >> 3;          // matrix index 0..3
    const int r = lane & 7;           // row within matrix

    // Per-lane precomputed ldmatrix address parts.
    uint32_t aRow[4], aXor[4];
#pragma unroll
    for (int mt = 0; mt < 4; mt++) {
        int row = warpM + mt * 16 + (j & 1) * 8 + r;
        aRow[mt] = (uint32_t)row * 128u;
        aXor[mt] = (uint32_t)(row & 7) << 4;
    }
    const uint32_t aKj = (uint32_t)(j >> 1);
    uint32_t bRow[4], bXor[4];
#pragma unroll
    for (int ntp = 0; ntp < 4; ntp++) {
        int row = warpN + ntp * 16 + (j >> 1) * 8 + r;
        bRow[ntp] = (uint32_t)row * 128u;
        bXor[ntp] = (uint32_t)(row & 7) << 4;
    }
    const uint32_t bKj = (uint32_t)(j & 1);

    float acc[4][8][4];
#pragma unroll
    for (int mt = 0; mt < 4; mt++)
#pragma unroll
        for (int nt = 0; nt < 8; nt++)
#pragma unroll
            for (int q = 0; q < 4; q++) acc[mt][nt][q] = 0.0f;

    // ---- producer: fill stage s with K-chunk at k0 ----
    auto fill = [&](int s, int k0) {
        uint32_t aB = sb + (uint32_t)s * STAGE_BYTES;
        uint32_t bB = aB + A_BYTES;
        const float* asrc = A + (size_t)(mBase + tid) * KDIM + k0;
        const float* bsrc = Bw + (size_t)(nBase + tid) * KDIM + k0;
        uint32_t rowp = (uint32_t)tid * 128u;
        uint32_t xv = (uint32_t)(tid & 7) << 4;
#pragma unroll
        for (int c = 0; c < 8; c++) {
            uint32_t co = ((uint32_t)c << 4) ^ xv;
            CP_ASYNC16(aB + rowp + co, asrc + c * 4);
            CP_ASYNC16(bB + rowp + co, bsrc + c * 4);
        }
    };

    fill(0, 0);        CP_COMMIT();
    fill(1, BK);       CP_COMMIT();

    int sComp = 0;     // stage being computed this iter
    int sFill = 2;     // stage to fill this iter (tile i+2)

    for (int i = 0; i < NITER; i++) {
        CP_WAIT1();            // per-thread: tile i resident
        __syncthreads();       // all threads' tile i visible; stage sFill free

        // issue next fill FIRST so loads overlap this iteration's MMAs
        int nk = (i + 2) * BK;
        if (nk < KDIM) fill(sFill, nk);
        CP_COMMIT();

        const uint32_t aBase = sb + (uint32_t)sComp * STAGE_BYTES;
        const uint32_t bBase = aBase + A_BYTES;

#pragma unroll
        for (int ks = 0; ks < 4; ks++) {
            const uint32_t kc0 = (uint32_t)ks * 2u;
            uint32_t af[4][4];
#pragma unroll
            for (int mt = 0; mt < 4; mt++) {
                uint32_t addr = aBase + aRow[mt] + ((((kc0 + aKj) << 4)) ^ aXor[mt]);
                LDSM_X4(af[mt][0], af[mt][1], af[mt][2], af[mt][3], addr);
            }
            uint32_t bf[8][2];
#pragma unroll
            for (int ntp = 0; ntp < 4; ntp++) {
                uint32_t addr = bBase + bRow[ntp] + ((((kc0 + bKj) << 4)) ^ bXor[ntp]);
                LDSM_X4(bf[2 * ntp][0], bf[2 * ntp][1],
                        bf[2 * ntp + 1][0], bf[2 * ntp + 1][1], addr);
            }
#pragma unroll
            for (int mt = 0; mt < 4; mt++)
#pragma unroll
                for (int nt = 0; nt < 8; nt++) {
                    asm volatile(
                        "mma.sync.aligned.m16n8k8.row.col.f32.tf32.tf32.f32 "
                        "{%0,%1,%2,%3}, {%4,%5,%6,%7}, {%8,%9}, {%0,%1,%2,%3};"
                        : "+f"(acc[mt][nt][0]), "+f"(acc[mt][nt][1]),
                          "+f"(acc[mt][nt][2]), "+f"(acc[mt][nt][3])
                        : "r"(af[mt][0]), "r"(af[mt][1]), "r"(af[mt][2]), "r"(af[mt][3]),
                          "r"(bf[nt][0]), "r"(bf[nt][1]));
                }
        }

        sComp = (sComp == NSTAGE - 1) ? 0 : sComp + 1;
        sFill = (sFill == NSTAGE - 1) ? 0 : sFill + 1;
    }

    // ---- epilogue: add bias, store ----
#pragma unroll
    for (int mt = 0; mt < 4; mt++) {
        int row0 = mBase + warpM + mt * 16 + g;
#pragma unroll
        for (int nt = 0; nt < 8; nt++) {
            int col = nBase + warpN + nt * 8 + 2 * t;
            float b0 = bias[col], b1 = bias[col + 1];
            float2 v0 = make_float2(acc[mt][nt][0] + b0, acc[mt][nt][1] + b1);
            float2 v1 = make_float2(acc[mt][nt][2] + b0, acc[mt][nt][3] + b1);
            *reinterpret_cast<float2*>(C + (size_t)row0 * 1024 + col) = v0;
            *reinterpret_cast<float2*>(C + (size_t)(row0 + 8) * 1024 + col) = v1;
        }
    }
}

// ---------------------------------------------------------------------------
// rna(tf32) conversion pass
// ---------------------------------------------------------------------------
__global__ __launch_bounds__(256) void conv_rna_kernel(
    const float* __restrict__ src, float* __restrict__ dst, int n4)
{
    int i = blockIdx.x * blockDim.x + threadIdx.x;
    if (i >= n4) return;
    float4 v = reinterpret_cast<const float4*>(src)[i];
    v.x = __uint_as_float(f2tf32(v.x));
    v.y = __uint_as_float(f2tf32(v.y));
    v.z = __uint_as_float(f2tf32(v.z));
    v.w = __uint_as_float(f2tf32(v.w));
    reinterpret_cast<float4*>(dst)[i] = v;
}

// ---------------------------------------------------------------------------
// Scan stage 1: per-(b, chunk, n) chunk-end state (read-only pass)
// ---------------------------------------------------------------------------
__global__ __launch_bounds__(256) void scan_ends_kernel(const float* __restrict__ log_A)
{
    int idx = blockIdx.x * blockDim.x + threadIdx.x;
    int n = idx & (N_STATE - 1);
    int c = (idx / N_STATE) & (NCHUNK - 1);
    int b = idx / (N_STATE * NCHUNK);
    if (b >= BATCH) return;

    const float Av = sigmoidf_(log_A[n]);
    size_t base = ((size_t)b * SEQ_T + (size_t)c * CHUNK) * N_STATE + n;
    float h = 0.0f;
#pragma unroll 4
    for (int tt = 0; tt < CHUNK; tt++)
        h = fmaf(Av, h, g_bx[base + (size_t)tt * N_STATE]);
    g_end[((size_t)b * NCHUNK + c) * N_STATE + n] = h;
}

// ---------------------------------------------------------------------------
// Scan stage 2: carry from ends, final inclusive scan; h written rna-rounded
// (it is GEMM2's A operand).
// ---------------------------------------------------------------------------
__global__ __launch_bounds__(256) void scan_apply_kernel(const float* __restrict__ log_A)
{
    int idx = blockIdx.x * blockDim.x + threadIdx.x;
    int n = idx & (N_STATE - 1);
    int c = (idx / N_STATE) & (NCHUNK - 1);
    int b = idx / (N_STATE * NCHUNK);
    if (b >= BATCH) return;

    const float Av = sigmoidf_(log_A[n]);
    float aL = Av;
#pragma unroll
    for (int s = 0; s < 7; s++) aL = aL * aL;

    float E = 0.0f;
    for (int cp = 0; cp < c; cp++)
        E = fmaf(aL, E, g_end[((size_t)b * NCHUNK + cp) * N_STATE + n]);

    size_t base = ((size_t)b * SEQ_T + (size_t)c * CHUNK) * N_STATE + n;
    float h = E;
#pragma unroll 4
    for (int tt = 0; tt < CHUNK; tt++) {
        size_t off = base + (size_t)tt * N_STATE;
        h = fmaf(Av, h, g_bx[off]);
        g_bx[off] = __uint_as_float(f2tf32(h));
    }
}

// ---------------------------------------------------------------------------
// Launch
// ---------------------------------------------------------------------------
extern "C" void kernel_launch(void* const* d_in, const int* in_sizes, int n_in,
                              void* d_out, int out_size)
{
    const float* x    = (const float*)d_in[0];   // [8, 2048, 1024]
    const float* logA = (const float*)d_in[1];   // [1024]
    const float* B_w  = (const float*)d_in[2];   // [1024, 1024] (N, D)
    const float* B_b  = (const float*)d_in[3];   // [1024]
    const float* C_w  = (const float*)d_in[4];   // [1024, 1024] (D, N)
    const float* C_b  = (const float*)d_in[5];   // [1024]
    float* y = (float*)d_out;                    // [8, 2048, 1024]

    float *bx, *xc, *w1, *w2;
    cudaGetSymbolAddress((void**)&bx, g_bx);
    cudaGetSymbolAddress((void**)&xc, g_xc);
    cudaGetSymbolAddress((void**)&w1, g_w1);
    cudaGetSymbolAddress((void**)&w2, g_w2);

    cudaFuncSetAttribute(gemm_tc_tf32, cudaFuncAttributeMaxDynamicSharedMemorySize,
                         SMEM_GEMM_TOTAL);

    // rna-round operands for tf32 MMA
    {
        int n4x = MROWS * D_MODEL / 4;
        conv_rna_kernel<<<n4x / 256, 256>>>(x, xc, n4x);
        int n4w = N_STATE * D_MODEL / 4;
        conv_rna_kernel<<<n4w / 256, 256>>>(B_w, w1, n4w);
        conv_rna_kernel<<<n4w / 256, 256>>>(C_w, w2, n4w);
    }

    // GEMM1: B_x = x @ B_w^T + B_b
    {
        dim3 grid(N_STATE / BN, MROWS / BM);   // (8, 128)
        gemm_tc_tf32<<<grid, 128, SMEM_GEMM_TOTAL>>>(xc, w1, B_b, bx);
    }

    // Scan (chunked, 2 passes; h written rna-rounded)
    {
        int total = BATCH * NCHUNK * N_STATE;
        scan_ends_kernel<<<total / 256, 256>>>(logA);
        scan_apply_kernel<<<total / 256, 256>>>(logA);
    }

    // GEMM2: y = h @ C_w^T + C_b
    {
        dim3 grid(D_MODEL / BN, MROWS / BM);   // (8, 128)
        gemm_tc_tf32<<<grid, 128, SMEM_GEMM_TOTAL>>>(bx, w2, C_b, y);
    }
}

// round 8
// speedup vs baseline: 1.0733x; 1.0733x over previous
#include <cuda_runtime.h>
#include <math.h>
#include <stdint.h>

// ---------------------------------------------------------------------------
// Problem shape (fixed)
// ---------------------------------------------------------------------------
constexpr int BATCH = 8;
constexpr int SEQ_T = 2048;
constexpr int D_MODEL = 1024;
constexpr int N_STATE = 1024;
constexpr int MROWS = BATCH * SEQ_T;      // 16384
constexpr int KDIM = 1024;
constexpr int CHUNK = 128;
constexpr int NCHUNK = SEQ_T / CHUNK;     // 16

// Scratch (no cudaMalloc allowed)
__device__ float g_bx[MROWS * N_STATE];                 // B_x -> h (rna'd by scan)
__device__ float g_xc[MROWS * D_MODEL];                 // rna(x)
__device__ float g_w1[N_STATE * D_MODEL];               // rna(B_w)
__device__ float g_w2[D_MODEL * N_STATE];               // rna(C_w)
__device__ float g_end[BATCH * NCHUNK * N_STATE];       // chunk-end states

__device__ __forceinline__ float sigmoidf_(float x) {
    return 1.0f / (1.0f + __expf(-x));
}
__device__ __forceinline__ uint32_t f2tf32(float x) {
    uint32_t r;
    asm("cvt.rna.tf32.f32 %0, %1;" : "=r"(r) : "f"(x));
    return r;
}
__device__ __forceinline__ uint32_t smem_u32(const void* p) {
    uint32_t a;
    asm("{ .reg .u64 t; cvta.to.shared.u64 t, %1; cvt.u32.u64 %0, t; }" : "=r"(a) : "l"(p));
    return a;
}

#define CP_ASYNC16(dst, src) \
    asm volatile("cp.async.cg.shared.global [%0], [%1], 16;" :: "r"(dst), "l"(src))
#define CP_COMMIT() asm volatile("cp.async.commit_group;" ::: "memory")
#define CP_WAIT1()  asm volatile("cp.async.wait_group 1;" ::: "memory")

#define LDSM_X4(r0, r1, r2, r3, addr) \
    asm volatile("ldmatrix.sync.aligned.m8n8.x4.shared.b16 {%0,%1,%2,%3}, [%4];" \
        : "=r"(r0), "=r"(r1), "=r"(r2), "=r"(r3) : "r"(addr))

// ---------------------------------------------------------------------------
// TF32 mma.sync GEMM: C[M,N=1024] = A[M,K]*B[N,K]^T + bias
// CTA tile 128x128x32, 4 warps (warp tile 64x64), 3-stage cp.async pipeline,
// register double-buffered fragments (LDSM for k-step s+1 overlaps MMAs of s).
// ---------------------------------------------------------------------------
constexpr int BM = 128, BN = 128, BK = 32;
constexpr int A_BYTES = BM * 128;                 // 16 KB (32 floats/row = 128B)
constexpr int B_BYTES = BN * 128;                 // 16 KB
constexpr int STAGE_BYTES = A_BYTES + B_BYTES;    // 32 KB
constexpr int NSTAGE = 3;
constexpr int SMEM_GEMM_TOTAL = NSTAGE * STAGE_BYTES;  // 96 KB
constexpr int NITER = KDIM / BK;                  // 32

__global__ __launch_bounds__(128, 2) void gemm_tc_tf32(
    const float* __restrict__ A, const float* __restrict__ Bw,
    const float* __restrict__ bias, float* __restrict__ C)
{
    extern __shared__ char smem[];
    const uint32_t sb = smem_u32(smem);
    const int tid = threadIdx.x;
    const int wid = tid >> 5;
    const int lane = tid & 31;
    const int g = lane >> 2;          // 0..7
    const int t = lane & 3;           // 0..3
    const int mBase = blockIdx.y * BM;
    const int nBase = blockIdx.x * BN;
    const int warpM = (wid >> 1) * 64;
    const int warpN = (wid & 1) * 64;

    // ldmatrix lane roles
    const int j = lane >> 3;          // matrix index 0..3
    const int r = lane & 7;           // row within matrix

    // Per-lane precomputed ldmatrix address parts.
    uint32_t aRow[4], aXor[4];
#pragma unroll
    for (int mt = 0; mt < 4; mt++) {
        int row = warpM + mt * 16 + (j & 1) * 8 + r;
        aRow[mt] = (uint32_t)row * 128u;
        aXor[mt] = (uint32_t)(row & 7) << 4;
    }
    const uint32_t aKj = (uint32_t)(j >> 1);
    uint32_t bRow[4], bXor[4];
#pragma unroll
    for (int ntp = 0; ntp < 4; ntp++) {
        int row = warpN + ntp * 16 + (j >> 1) * 8 + r;
        bRow[ntp] = (uint32_t)row * 128u;
        bXor[ntp] = (uint32_t)(row & 7) << 4;
    }
    const uint32_t bKj = (uint32_t)(j & 1);

    float acc[4][8][4];
#pragma unroll
    for (int mt = 0; mt < 4; mt++)
#pragma unroll
        for (int nt = 0; nt < 8; nt++)
#pragma unroll
            for (int q = 0; q < 4; q++) acc[mt][nt][q] = 0.0f;

    // Double-buffered fragments
    uint32_t af[2][4][4];
    uint32_t bf[2][8][2];

    // ---- producer: fill stage s with K-chunk at k0 ----
    auto fill = [&](int s, int k0) {
        uint32_t aB = sb + (uint32_t)s * STAGE_BYTES;
        uint32_t bB = aB + A_BYTES;
        const float* asrc = A + (size_t)(mBase + tid) * KDIM + k0;
        const float* bsrc = Bw + (size_t)(nBase + tid) * KDIM + k0;
        uint32_t rowp = (uint32_t)tid * 128u;
        uint32_t xv = (uint32_t)(tid & 7) << 4;
#pragma unroll
        for (int c = 0; c < 8; c++) {
            uint32_t co = ((uint32_t)c << 4) ^ xv;
            CP_ASYNC16(aB + rowp + co, asrc + c * 4);
            CP_ASYNC16(bB + rowp + co, bsrc + c * 4);
        }
    };

    // ---- fragment loader: k-step ksIdx from stage base into buffer bi ----
    auto loadFrags = [&](uint32_t aBase, uint32_t bBase, int ksIdx, int bi) {
        const uint32_t kc0 = (uint32_t)ksIdx * 2u;
#pragma unroll
        for (int mt = 0; mt < 4; mt++) {
            uint32_t addr = aBase + aRow[mt] + ((((kc0 + aKj) << 4)) ^ aXor[mt]);
            LDSM_X4(af[bi][mt][0], af[bi][mt][1], af[bi][mt][2], af[bi][mt][3], addr);
        }
#pragma unroll
        for (int ntp = 0; ntp < 4; ntp++) {
            uint32_t addr = bBase + bRow[ntp] + ((((kc0 + bKj) << 4)) ^ bXor[ntp]);
            LDSM_X4(bf[bi][2 * ntp][0], bf[bi][2 * ntp][1],
                    bf[bi][2 * ntp + 1][0], bf[bi][2 * ntp + 1][1], addr);
        }
    };

    fill(0, 0);        CP_COMMIT();
    fill(1, BK);       CP_COMMIT();

    int sComp = 0;     // stage being computed this iter
    int sFill = 2;     // stage to fill this iter (tile i+2)

    for (int i = 0; i < NITER; i++) {
        CP_WAIT1();            // per-thread: tile i resident
        __syncthreads();       // all threads' tile i visible; stage sFill free

        const uint32_t aBase = sb + (uint32_t)sComp * STAGE_BYTES;
        const uint32_t bBase = aBase + A_BYTES;

        // prefetch k-step 0 fragments first ...
        loadFrags(aBase, bBase, 0, 0);

        // ... then issue the global prefetch (overlaps with MMA work below)
        int nk = (i + 2) * BK;
        if (nk < KDIM) fill(sFill, nk);
        CP_COMMIT();

#pragma unroll
        for (int ks = 0; ks < 4; ks++) {
            const int cur = ks & 1;
            if (ks < 3) loadFrags(aBase, bBase, ks + 1, cur ^ 1);
#pragma unroll
            for (int mt = 0; mt < 4; mt++)
#pragma unroll
                for (int nt = 0; nt < 8; nt++) {
                    asm volatile(
                        "mma.sync.aligned.m16n8k8.row.col.f32.tf32.tf32.f32 "
                        "{%0,%1,%2,%3}, {%4,%5,%6,%7}, {%8,%9}, {%0,%1,%2,%3};"
                        : "+f"(acc[mt][nt][0]), "+f"(acc[mt][nt][1]),
                          "+f"(acc[mt][nt][2]), "+f"(acc[mt][nt][3])
                        : "r"(af[cur][mt][0]), "r"(af[cur][mt][1]),
                          "r"(af[cur][mt][2]), "r"(af[cur][mt][3]),
                          "r"(bf[cur][nt][0]), "r"(bf[cur][nt][1]));
                }
        }

        sComp = (sComp == NSTAGE - 1) ? 0 : sComp + 1;
        sFill = (sFill == NSTAGE - 1) ? 0 : sFill + 1;
    }

    // ---- epilogue: add bias, store ----
#pragma unroll
    for (int mt = 0; mt < 4; mt++) {
        int row0 = mBase + warpM + mt * 16 + g;
#pragma unroll
        for (int nt = 0; nt < 8; nt++) {
            int col = nBase + warpN + nt * 8 + 2 * t;
            float b0 = bias[col], b1 = bias[col + 1];
            float2 v0 = make_float2(acc[mt][nt][0] + b0, acc[mt][nt][1] + b1);
            float2 v1 = make_float2(acc[mt][nt][2] + b0, acc[mt][nt][3] + b1);
            *reinterpret_cast<float2*>(C + (size_t)row0 * 1024 + col) = v0;
            *reinterpret_cast<float2*>(C + (size_t)(row0 + 8) * 1024 + col) = v1;
        }
    }
}

// ---------------------------------------------------------------------------
// rna(tf32) conversion pass
// ---------------------------------------------------------------------------
__global__ __launch_bounds__(256) void conv_rna_kernel(
    const float* __restrict__ src, float* __restrict__ dst, int n4)
{
    int i = blockIdx.x * blockDim.x + threadIdx.x;
    if (i >= n4) return;
    float4 v = reinterpret_cast<const float4*>(src)[i];
    v.x = __uint_as_float(f2tf32(v.x));
    v.y = __uint_as_float(f2tf32(v.y));
    v.z = __uint_as_float(f2tf32(v.z));
    v.w = __uint_as_float(f2tf32(v.w));
    reinterpret_cast<float4*>(dst)[i] = v;
}

// ---------------------------------------------------------------------------
// Scan stage 1: per-(b, chunk, n) chunk-end state (read-only pass)
// ---------------------------------------------------------------------------
__global__ __launch_bounds__(256) void scan_ends_kernel(const float* __restrict__ log_A)
{
    int idx = blockIdx.x * blockDim.x + threadIdx.x;
    int n = idx & (N_STATE - 1);
    int c = (idx / N_STATE) & (NCHUNK - 1);
    int b = idx / (N_STATE * NCHUNK);
    if (b >= BATCH) return;

    const float Av = sigmoidf_(log_A[n]);
    size_t base = ((size_t)b * SEQ_T + (size_t)c * CHUNK) * N_STATE + n;
    float h = 0.0f;
#pragma unroll 4
    for (int tt = 0; tt < CHUNK; tt++)
        h = fmaf(Av, h, g_bx[base + (size_t)tt * N_STATE]);
    g_end[((size_t)b * NCHUNK + c) * N_STATE + n] = h;
}

// ---------------------------------------------------------------------------
// Scan stage 2: carry from ends, final inclusive scan; h written rna-rounded
// (it is GEMM2's A operand).
// ---------------------------------------------------------------------------
__global__ __launch_bounds__(256) void scan_apply_kernel(const float* __restrict__ log_A)
{
    int idx = blockIdx.x * blockDim.x + threadIdx.x;
    int n = idx & (N_STATE - 1);
    int c = (idx / N_STATE) & (NCHUNK - 1);
    int b = idx / (N_STATE * NCHUNK);
    if (b >= BATCH) return;

    const float Av = sigmoidf_(log_A[n]);
    float aL = Av;
#pragma unroll
    for (int s = 0; s < 7; s++) aL = aL * aL;

    float E = 0.0f;
    for (int cp = 0; cp < c; cp++)
        E = fmaf(aL, E, g_end[((size_t)b * NCHUNK + cp) * N_STATE + n]);

    size_t base = ((size_t)b * SEQ_T + (size_t)c * CHUNK) * N_STATE + n;
    float h = E;
#pragma unroll 4
    for (int tt = 0; tt < CHUNK; tt++) {
        size_t off = base + (size_t)tt * N_STATE;
        h = fmaf(Av, h, g_bx[off]);
        g_bx[off] = __uint_as_float(f2tf32(h));
    }
}

// ---------------------------------------------------------------------------
// Launch
// ---------------------------------------------------------------------------
extern "C" void kernel_launch(void* const* d_in, const int* in_sizes, int n_in,
                              void* d_out, int out_size)
{
    const float* x    = (const float*)d_in[0];   // [8, 2048, 1024]
    const float* logA = (const float*)d_in[1];   // [1024]
    const float* B_w  = (const float*)d_in[2];   // [1024, 1024] (N, D)
    const float* B_b  = (const float*)d_in[3];   // [1024]
    const float* C_w  = (const float*)d_in[4];   // [1024, 1024] (D, N)
    const float* C_b  = (const float*)d_in[5];   // [1024]
    float* y = (float*)d_out;                    // [8, 2048, 1024]

    float *bx, *xc, *w1, *w2;
    cudaGetSymbolAddress((void**)&bx, g_bx);
    cudaGetSymbolAddress((void**)&xc, g_xc);
    cudaGetSymbolAddress((void**)&w1, g_w1);
    cudaGetSymbolAddress((void**)&w2, g_w2);

    cudaFuncSetAttribute(gemm_tc_tf32, cudaFuncAttributeMaxDynamicSharedMemorySize,
                         SMEM_GEMM_TOTAL);

    // rna-round operands for tf32 MMA
    {
        int n4x = MROWS * D_MODEL / 4;
        conv_rna_kernel<<<n4x / 256, 256>>>(x, xc, n4x);
        int n4w = N_STATE * D_MODEL / 4;
        conv_rna_kernel<<<n4w / 256, 256>>>(B_w, w1, n4w);
        conv_rna_kernel<<<n4w / 256, 256>>>(C_w, w2, n4w);
    }

    // GEMM1: B_x = x @ B_w^T + B_b
    {
        dim3 grid(N_STATE / BN, MROWS / BM);   // (8, 128)
        gemm_tc_tf32<<<grid, 128, SMEM_GEMM_TOTAL>>>(xc, w1, B_b, bx);
    }

    // Scan (chunked, 2 passes; h written rna-rounded)
    {
        int total = BATCH * NCHUNK * N_STATE;
        scan_ends_kernel<<<total / 256, 256>>>(logA);
        scan_apply_kernel<<<total / 256, 256>>>(logA);
    }

    // GEMM2: y = h @ C_w^T + C_b
    {
        dim3 grid(D_MODEL / BN, MROWS / BM);   // (8, 128)
        gemm_tc_tf32<<<grid, 128, SMEM_GEMM_TOTAL>>>(bx, w2, C_b, y);
    }
}

// round 9
// speedup vs baseline: 1.7244x; 1.6067x over previous
#include <cuda_runtime.h>
#include <math.h>
#include <stdint.h>

// ---------------------------------------------------------------------------
// Problem shape (fixed)
// ---------------------------------------------------------------------------
constexpr int BATCH = 8;
constexpr int SEQ_T = 2048;
constexpr int D_MODEL = 1024;
constexpr int N_STATE = 1024;
constexpr int MROWS = BATCH * SEQ_T;      // 16384
constexpr int KDIM = 1024;
constexpr int CHUNK = 128;
constexpr int NCHUNK = SEQ_T / CHUNK;     // 16

// Scratch (no cudaMalloc allowed)
__device__ float g_bx[MROWS * N_STATE];                 // B_x -> h (rna'd by scan)
__device__ float g_xc[MROWS * D_MODEL];                 // rna(x)
__device__ float g_w1[N_STATE * D_MODEL];               // rna(B_w)
__device__ float g_w2[D_MODEL * N_STATE];               // rna(C_w)
__device__ float g_end[BATCH * NCHUNK * N_STATE];       // chunk-end states

__device__ __forceinline__ float sigmoidf_(float x) {
    return 1.0f / (1.0f + __expf(-x));
}
__device__ __forceinline__ uint32_t f2tf32(float x) {
    uint32_t r;
    asm("cvt.rna.tf32.f32 %0, %1;" : "=r"(r) : "f"(x));
    return r;
}
__device__ __forceinline__ uint32_t smem_u32(const void* p) {
    uint32_t a;
    asm("{ .reg .u64 t; cvta.to.shared.u64 t, %1; cvt.u32.u64 %0, t; }" : "=r"(a) : "l"(p));
    return a;
}

#define CP_ASYNC16(dst, src) \
    asm volatile("cp.async.cg.shared.global [%0], [%1], 16;" :: "r"(dst), "l"(src))
#define CP_COMMIT() asm volatile("cp.async.commit_group;" ::: "memory")
#define CP_WAIT2()  asm volatile("cp.async.wait_group 2;" ::: "memory")

#define LDSM_X4(r0, r1, r2, r3, addr) \
    asm volatile("ldmatrix.sync.aligned.m8n8.x4.shared.b16 {%0,%1,%2,%3}, [%4];" \
        : "=r"(r0), "=r"(r1), "=r"(r2), "=r"(r3) : "r"(addr))

// ---------------------------------------------------------------------------
// TF32 mma.sync GEMM: C[M,N=1024] = A[M,K]*B[N,K]^T + bias
// CTA tile 128x256x32 (8 warps, warp tile 64x64), 4-stage cp.async pipeline,
// register double-buffered fragments. Cuts L2 traffic 25% vs 128x128 tiles.
// ---------------------------------------------------------------------------
constexpr int BM = 128, BN = 256, BK = 32;
constexpr int A_BYTES = BM * 128;                 // 16 KB (32 floats/row = 128B)
constexpr int B_BYTES = BN * 128;                 // 32 KB
constexpr int STAGE_BYTES = A_BYTES + B_BYTES;    // 48 KB
constexpr int NSTAGE = 4;
constexpr int SMEM_GEMM_TOTAL = NSTAGE * STAGE_BYTES;  // 192 KB
constexpr int NITER = KDIM / BK;                  // 32
constexpr int TOTAL_ROWS = BM + BN;               // 384 rows per stage
constexpr int CHUNKS_PER_THREAD = TOTAL_ROWS * 8 / 256;  // 12

__global__ __launch_bounds__(256, 1) void gemm_tc_tf32(
    const float* __restrict__ A, const float* __restrict__ Bw,
    const float* __restrict__ bias, float* __restrict__ C)
{
    extern __shared__ char smem[];
    const uint32_t sb = smem_u32(smem);
    const int tid = threadIdx.x;
    const int wid = tid >> 5;
    const int lane = tid & 31;
    const int g = lane >> 2;          // 0..7
    const int t = lane & 3;           // 0..3
    const int mBase = blockIdx.y * BM;
    const int nBase = blockIdx.x * BN;
    const int warpM = (wid & 1) * 64;         // 2 warps along M (128)
    const int warpN = (wid >> 1) * 64;        // 4 warps along N (256)

    // ldmatrix lane roles
    const int j = lane >> 3;          // matrix index 0..3
    const int r = lane & 7;           // row within matrix

    // Per-lane precomputed ldmatrix address parts.
    uint32_t aRow[4], aXor[4];
#pragma unroll
    for (int mt = 0; mt < 4; mt++) {
        int row = warpM + mt * 16 + (j & 1) * 8 + r;
        aRow[mt] = (uint32_t)row * 128u;
        aXor[mt] = (uint32_t)(row & 7) << 4;
    }
    const uint32_t aKj = (uint32_t)(j >> 1);
    uint32_t bRow[4], bXor[4];
#pragma unroll
    for (int ntp = 0; ntp < 4; ntp++) {
        int row = warpN + ntp * 16 + (j >> 1) * 8 + r;
        bRow[ntp] = (uint32_t)row * 128u;
        bXor[ntp] = (uint32_t)(row & 7) << 4;
    }
    const uint32_t bKj = (uint32_t)(j & 1);

    float acc[4][8][4];
#pragma unroll
    for (int mt = 0; mt < 4; mt++)
#pragma unroll
        for (int nt = 0; nt < 8; nt++)
#pragma unroll
            for (int q = 0; q < 4; q++) acc[mt][nt][q] = 0.0f;

    // Double-buffered fragments
    uint32_t af[2][4][4];
    uint32_t bf[2][8][2];

    // ---- producer: fill stage s with K-chunk at k0.
    //      Rows 0..127 = A tile, rows 128..383 = B tile (B base = +16KB). ----
    auto fill = [&](int s, int k0) {
        uint32_t stBase = sb + (uint32_t)s * STAGE_BYTES;
#pragma unroll
        for (int q = 0; q < CHUNKS_PER_THREAD; q++) {
            int idx = q * 256 + tid;            // 0..3071
            int row = idx >> 3;                 // 0..383
            int col = idx & 7;
            uint32_t off = (uint32_t)row * 128u +
                           (((uint32_t)col << 4) ^ ((uint32_t)(row & 7) << 4));
            const float* src = (row < BM)
                ? A  + (size_t)(mBase + row) * KDIM + k0 + col * 4
                : Bw + (size_t)(nBase + row - BM) * KDIM + k0 + col * 4;
            CP_ASYNC16(stBase + off, src);
        }
    };

    // ---- fragment loader: k-step ksIdx from stage base into buffer bi ----
    auto loadFrags = [&](uint32_t aBase, uint32_t bBase, int ksIdx, int bi) {
        const uint32_t kc0 = (uint32_t)ksIdx * 2u;
#pragma unroll
        for (int mt = 0; mt < 4; mt++) {
            uint32_t addr = aBase + aRow[mt] + ((((kc0 + aKj) << 4)) ^ aXor[mt]);
            LDSM_X4(af[bi][mt][0], af[bi][mt][1], af[bi][mt][2], af[bi][mt][3], addr);
        }
#pragma unroll
        for (int ntp = 0; ntp < 4; ntp++) {
            uint32_t addr = bBase + bRow[ntp] + ((((kc0 + bKj) << 4)) ^ bXor[ntp]);
            LDSM_X4(bf[bi][2 * ntp][0], bf[bi][2 * ntp][1],
                    bf[bi][2 * ntp + 1][0], bf[bi][2 * ntp + 1][1], addr);
        }
    };

    fill(0, 0);        CP_COMMIT();
    fill(1, BK);       CP_COMMIT();
    fill(2, 2 * BK);   CP_COMMIT();

    int sComp = 0;     // stage computed this iter
    int sFill = 3;     // stage filled this iter (tile i+3)

    for (int i = 0; i < NITER; i++) {
        CP_WAIT2();            // tile i resident (<=2 younger groups pending)
        __syncthreads();       // visibility + stage sFill free

        const uint32_t aBase = sb + (uint32_t)sComp * STAGE_BYTES;
        const uint32_t bBase = aBase + A_BYTES;

        // prefetch k-step 0 fragments first ...
        loadFrags(aBase, bBase, 0, 0);

        // ... then issue the global prefetch (overlaps MMA work below)
        int nk = (i + 3) * BK;
        if (nk < KDIM) fill(sFill, nk);
        CP_COMMIT();

#pragma unroll
        for (int ks = 0; ks < 4; ks++) {
            const int cur = ks & 1;
            if (ks < 3) loadFrags(aBase, bBase, ks + 1, cur ^ 1);
#pragma unroll
            for (int mt = 0; mt < 4; mt++)
#pragma unroll
                for (int nt = 0; nt < 8; nt++) {
                    asm volatile(
                        "mma.sync.aligned.m16n8k8.row.col.f32.tf32.tf32.f32 "
                        "{%0,%1,%2,%3}, {%4,%5,%6,%7}, {%8,%9}, {%0,%1,%2,%3};"
                        : "+f"(acc[mt][nt][0]), "+f"(acc[mt][nt][1]),
                          "+f"(acc[mt][nt][2]), "+f"(acc[mt][nt][3])
                        : "r"(af[cur][mt][0]), "r"(af[cur][mt][1]),
                          "r"(af[cur][mt][2]), "r"(af[cur][mt][3]),
                          "r"(bf[cur][nt][0]), "r"(bf[cur][nt][1]));
                }
        }

        sComp = (sComp == NSTAGE - 1) ? 0 : sComp + 1;
        sFill = (sFill == NSTAGE - 1) ? 0 : sFill + 1;
    }

    // ---- epilogue: add bias, store ----
#pragma unroll
    for (int mt = 0; mt < 4; mt++) {
        int row0 = mBase + warpM + mt * 16 + g;
#pragma unroll
        for (int nt = 0; nt < 8; nt++) {
            int col = nBase + warpN + nt * 8 + 2 * t;
            float b0 = bias[col], b1 = bias[col + 1];
            float2 v0 = make_float2(acc[mt][nt][0] + b0, acc[mt][nt][1] + b1);
            float2 v1 = make_float2(acc[mt][nt][2] + b0, acc[mt][nt][3] + b1);
            *reinterpret_cast<float2*>(C + (size_t)row0 * 1024 + col) = v0;
            *reinterpret_cast<float2*>(C + (size_t)(row0 + 8) * 1024 + col) = v1;
        }
    }
}

// ---------------------------------------------------------------------------
// rna(tf32) conversion pass
// ---------------------------------------------------------------------------
__global__ __launch_bounds__(256) void conv_rna_kernel(
    const float* __restrict__ src, float* __restrict__ dst, int n4)
{
    int i = blockIdx.x * blockDim.x + threadIdx.x;
    if (i >= n4) return;
    float4 v = reinterpret_cast<const float4*>(src)[i];
    v.x = __uint_as_float(f2tf32(v.x));
    v.y = __uint_as_float(f2tf32(v.y));
    v.z = __uint_as_float(f2tf32(v.z));
    v.w = __uint_as_float(f2tf32(v.w));
    reinterpret_cast<float4*>(dst)[i] = v;
}

// ---------------------------------------------------------------------------
// Scan stage 1: per-(b, chunk, n) chunk-end state (read-only pass)
// ---------------------------------------------------------------------------
__global__ __launch_bounds__(256) void scan_ends_kernel(const float* __restrict__ log_A)
{
    int idx = blockIdx.x * blockDim.x + threadIdx.x;
    int n = idx & (N_STATE - 1);
    int c = (idx / N_STATE) & (NCHUNK - 1);
    int b = idx / (N_STATE * NCHUNK);
    if (b >= BATCH) return;

    const float Av = sigmoidf_(log_A[n]);
    size_t base = ((size_t)b * SEQ_T + (size_t)c * CHUNK) * N_STATE + n;
    float h = 0.0f;
#pragma unroll 4
    for (int tt = 0; tt < CHUNK; tt++)
        h = fmaf(Av, h, g_bx[base + (size_t)tt * N_STATE]);
    g_end[((size_t)b * NCHUNK + c) * N_STATE + n] = h;
}

// ---------------------------------------------------------------------------
// Scan stage 2: carry from ends, final inclusive scan; h written rna-rounded
// (it is GEMM2's A operand).
// ---------------------------------------------------------------------------
__global__ __launch_bounds__(256) void scan_apply_kernel(const float* __restrict__ log_A)
{
    int idx = blockIdx.x * blockDim.x + threadIdx.x;
    int n = idx & (N_STATE - 1);
    int c = (idx / N_STATE) & (NCHUNK - 1);
    int b = idx / (N_STATE * NCHUNK);
    if (b >= BATCH) return;

    const float Av = sigmoidf_(log_A[n]);
    float aL = Av;
#pragma unroll
    for (int s = 0; s < 7; s++) aL = aL * aL;

    float E = 0.0f;
    for (int cp = 0; cp < c; cp++)
        E = fmaf(aL, E, g_end[((size_t)b * NCHUNK + cp) * N_STATE + n]);

    size_t base = ((size_t)b * SEQ_T + (size_t)c * CHUNK) * N_STATE + n;
    float h = E;
#pragma unroll 4
    for (int tt = 0; tt < CHUNK; tt++) {
        size_t off = base + (size_t)tt * N_STATE;
        h = fmaf(Av, h, g_bx[off]);
        g_bx[off] = __uint_as_float(f2tf32(h));
    }
}

// ---------------------------------------------------------------------------
// Launch
// ---------------------------------------------------------------------------
extern "C" void kernel_launch(void* const* d_in, const int* in_sizes, int n_in,
                              void* d_out, int out_size)
{
    const float* x    = (const float*)d_in[0];   // [8, 2048, 1024]
    const float* logA = (const float*)d_in[1];   // [1024]
    const float* B_w  = (const float*)d_in[2];   // [1024, 1024] (N, D)
    const float* B_b  = (const float*)d_in[3];   // [1024]
    const float* C_w  = (const float*)d_in[4];   // [1024, 1024] (D, N)
    const float* C_b  = (const float*)d_in[5];   // [1024]
    float* y = (float*)d_out;                    // [8, 2048, 1024]

    float *bx, *xc, *w1, *w2;
    cudaGetSymbolAddress((void**)&bx, g_bx);
    cudaGetSymbolAddress((void**)&xc, g_xc);
    cudaGetSymbolAddress((void**)&w1, g_w1);
    cudaGetSymbolAddress((void**)&w2, g_w2);

    cudaFuncSetAttribute(gemm_tc_tf32, cudaFuncAttributeMaxDynamicSharedMemorySize,
                         SMEM_GEMM_TOTAL);

    // rna-round operands for tf32 MMA
    {
        int n4x = MROWS * D_MODEL / 4;
        conv_rna_kernel<<<n4x / 256, 256>>>(x, xc, n4x);
        int n4w = N_STATE * D_MODEL / 4;
        conv_rna_kernel<<<n4w / 256, 256>>>(B_w, w1, n4w);
        conv_rna_kernel<<<n4w / 256, 256>>>(C_w, w2, n4w);
    }

    // GEMM1: B_x = x @ B_w^T + B_b
    {
        dim3 grid(N_STATE / BN, MROWS / BM);   // (4, 128)
        gemm_tc_tf32<<<grid, 256, SMEM_GEMM_TOTAL>>>(xc, w1, B_b, bx);
    }

    // Scan (chunked, 2 passes; h written rna-rounded)
    {
        int total = BATCH * NCHUNK * N_STATE;
        scan_ends_kernel<<<total / 256, 256>>>(logA);
        scan_apply_kernel<<<total / 256, 256>>>(logA);
    }

    // GEMM2: y = h @ C_w^T + C_b
    {
        dim3 grid(D_MODEL / BN, MROWS / BM);   // (4, 128)
        gemm_tc_tf32<<<grid, 256, SMEM_GEMM_TOTAL>>>(bx, w2, C_b, y);
    }
}

// round 10
// speedup vs baseline: 1.7402x; 1.0092x over previous
#include <cuda_runtime.h>
#include <math.h>
#include <stdint.h>

// ---------------------------------------------------------------------------
// Problem shape (fixed)
// ---------------------------------------------------------------------------
constexpr int BATCH = 8;
constexpr int SEQ_T = 2048;
constexpr int D_MODEL = 1024;
constexpr int N_STATE = 1024;
constexpr int MROWS = BATCH * SEQ_T;      // 16384
constexpr int KDIM = 1024;
constexpr int CHUNK = 128;
constexpr int NCHUNK = SEQ_T / CHUNK;     // 16

// Scratch (no cudaMalloc allowed)
__device__ float g_bx[MROWS * N_STATE];                 // B_x -> h (rna'd by scan)
__device__ float g_xc[MROWS * D_MODEL];                 // rna(x)
__device__ float g_w1[N_STATE * D_MODEL];               // rna(B_w)
__device__ float g_w2[D_MODEL * N_STATE];               // rna(C_w)
__device__ float g_end[BATCH * NCHUNK * N_STATE];       // chunk-end states

__device__ __forceinline__ float sigmoidf_(float x) {
    return 1.0f / (1.0f + __expf(-x));
}
__device__ __forceinline__ uint32_t f2tf32(float x) {
    uint32_t r;
    asm("cvt.rna.tf32.f32 %0, %1;" : "=r"(r) : "f"(x));
    return r;
}
__device__ __forceinline__ uint32_t smem_u32(const void* p) {
    uint32_t a;
    asm("{ .reg .u64 t; cvta.to.shared.u64 t, %1; cvt.u32.u64 %0, t; }" : "=r"(a) : "l"(p));
    return a;
}

#define CP_ASYNC16(dst, src) \
    asm volatile("cp.async.cg.shared.global [%0], [%1], 16;" :: "r"(dst), "l"(src))
#define CP_COMMIT() asm volatile("cp.async.commit_group;" ::: "memory")
#define CP_WAIT2()  asm volatile("cp.async.wait_group 2;" ::: "memory")

#define LDSM_X4(r0, r1, r2, r3, addr) \
    asm volatile("ldmatrix.sync.aligned.m8n8.x4.shared.b16 {%0,%1,%2,%3}, [%4];" \
        : "=r"(r0), "=r"(r1), "=r"(r2), "=r"(r3) : "r"(addr))

// ---------------------------------------------------------------------------
// TF32 mma.sync GEMM: C[M,N=1024] = A[M,K]*B[N,K]^T + bias
// CTA tile 128x256x32, 512 threads / 16 warps (warp tile 64x32), 4-stage
// cp.async pipeline. 4 warps/SMSP hide LDSM + fill latency.
// ---------------------------------------------------------------------------
constexpr int BM = 128, BN = 256, BK = 32;
constexpr int A_BYTES = BM * 128;                 // 16 KB (32 floats/row = 128B)
constexpr int B_BYTES = BN * 128;                 // 32 KB
constexpr int STAGE_BYTES = A_BYTES + B_BYTES;    // 48 KB
constexpr int NSTAGE = 4;
constexpr int SMEM_GEMM_TOTAL = NSTAGE * STAGE_BYTES;  // 192 KB
constexpr int NITER = KDIM / BK;                  // 32
constexpr int NTHREADS = 512;
constexpr int TOTAL_ROWS = BM + BN;               // 384 rows per stage
constexpr int CHUNKS_PER_THREAD = TOTAL_ROWS * 8 / NTHREADS;  // 6

__global__ __launch_bounds__(NTHREADS, 1) void gemm_tc_tf32(
    const float* __restrict__ A, const float* __restrict__ Bw,
    const float* __restrict__ bias, float* __restrict__ C)
{
    extern __shared__ char smem[];
    const uint32_t sb = smem_u32(smem);
    const int tid = threadIdx.x;
    const int wid = tid >> 5;          // 0..15
    const int lane = tid & 31;
    const int g = lane >> 2;           // 0..7
    const int t = lane & 3;            // 0..3
    const int mBase = blockIdx.y * BM;
    const int nBase = blockIdx.x * BN;
    const int warpM = (wid & 1) * 64;          // 2 warps along M (128)
    const int warpN = (wid >> 1) * 32;         // 8 warps along N (256)

    // ldmatrix lane roles
    const int j = lane >> 3;          // matrix index 0..3
    const int r = lane & 7;           // row within matrix

    // Per-lane precomputed ldmatrix address parts.
    uint32_t aRow[4], aXor[4];
#pragma unroll
    for (int mt = 0; mt < 4; mt++) {
        int row = warpM + mt * 16 + (j & 1) * 8 + r;
        aRow[mt] = (uint32_t)row * 128u;
        aXor[mt] = (uint32_t)(row & 7) << 4;
    }
    const uint32_t aKj = (uint32_t)(j >> 1);
    uint32_t bRow[2], bXor[2];
#pragma unroll
    for (int ntp = 0; ntp < 2; ntp++) {
        int row = warpN + ntp * 16 + (j >> 1) * 8 + r;
        bRow[ntp] = (uint32_t)row * 128u;
        bXor[ntp] = (uint32_t)(row & 7) << 4;
    }
    const uint32_t bKj = (uint32_t)(j & 1);

    float acc[4][4][4];
#pragma unroll
    for (int mt = 0; mt < 4; mt++)
#pragma unroll
        for (int nt = 0; nt < 4; nt++)
#pragma unroll
            for (int q = 0; q < 4; q++) acc[mt][nt][q] = 0.0f;

    uint32_t af[4][4];
    uint32_t bf[4][2];

    // ---- producer: fill stage s with K-chunk at k0.
    //      Rows 0..127 = A tile, rows 128..383 = B tile (B base = +16KB). ----
    auto fill = [&](int s, int k0) {
        uint32_t stBase = sb + (uint32_t)s * STAGE_BYTES;
#pragma unroll
        for (int q = 0; q < CHUNKS_PER_THREAD; q++) {
            int idx = q * NTHREADS + tid;       // 0..3071
            int row = idx >> 3;                 // 0..383
            int col = idx & 7;
            uint32_t off = (uint32_t)row * 128u +
                           (((uint32_t)col << 4) ^ ((uint32_t)(row & 7) << 4));
            const float* src = (row < BM)
                ? A  + (size_t)(mBase + row) * KDIM + k0 + col * 4
                : Bw + (size_t)(nBase + row - BM) * KDIM + k0 + col * 4;
            CP_ASYNC16(stBase + off, src);
        }
    };

    fill(0, 0);        CP_COMMIT();
    fill(1, BK);       CP_COMMIT();
    fill(2, 2 * BK);   CP_COMMIT();

    int sComp = 0;     // stage computed this iter
    int sFill = 3;     // stage filled this iter (tile i+3)

    for (int i = 0; i < NITER; i++) {
        CP_WAIT2();            // tile i resident (<=2 younger groups pending)
        __syncthreads();       // visibility + stage sFill free

        const uint32_t aBase = sb + (uint32_t)sComp * STAGE_BYTES;
        const uint32_t bBase = aBase + A_BYTES;

        // issue the global prefetch first (overlaps MMA work below)
        int nk = (i + 3) * BK;
        if (nk < KDIM) fill(sFill, nk);
        CP_COMMIT();

#pragma unroll
        for (int ks = 0; ks < 4; ks++) {
            const uint32_t kc0 = (uint32_t)ks * 2u;
#pragma unroll
            for (int mt = 0; mt < 4; mt++) {
                uint32_t addr = aBase + aRow[mt] + ((((kc0 + aKj) << 4)) ^ aXor[mt]);
                LDSM_X4(af[mt][0], af[mt][1], af[mt][2], af[mt][3], addr);
            }
#pragma unroll
            for (int ntp = 0; ntp < 2; ntp++) {
                uint32_t addr = bBase + bRow[ntp] + ((((kc0 + bKj) << 4)) ^ bXor[ntp]);
                LDSM_X4(bf[2 * ntp][0], bf[2 * ntp][1],
                        bf[2 * ntp + 1][0], bf[2 * ntp + 1][1], addr);
            }
#pragma unroll
            for (int mt = 0; mt < 4; mt++)
#pragma unroll
                for (int nt = 0; nt < 4; nt++) {
                    asm volatile(
                        "mma.sync.aligned.m16n8k8.row.col.f32.tf32.tf32.f32 "
                        "{%0,%1,%2,%3}, {%4,%5,%6,%7}, {%8,%9}, {%0,%1,%2,%3};"
                        : "+f"(acc[mt][nt][0]), "+f"(acc[mt][nt][1]),
                          "+f"(acc[mt][nt][2]), "+f"(acc[mt][nt][3])
                        : "r"(af[mt][0]), "r"(af[mt][1]),
                          "r"(af[mt][2]), "r"(af[mt][3]),
                          "r"(bf[nt][0]), "r"(bf[nt][1]));
                }
        }

        sComp = (sComp == NSTAGE - 1) ? 0 : sComp + 1;
        sFill = (sFill == NSTAGE - 1) ? 0 : sFill + 1;
    }

    // ---- epilogue: add bias, store ----
#pragma unroll
    for (int mt = 0; mt < 4; mt++) {
        int row0 = mBase + warpM + mt * 16 + g;
#pragma unroll
        for (int nt = 0; nt < 4; nt++) {
            int col = nBase + warpN + nt * 8 + 2 * t;
            float b0 = bias[col], b1 = bias[col + 1];
            float2 v0 = make_float2(acc[mt][nt][0] + b0, acc[mt][nt][1] + b1);
            float2 v1 = make_float2(acc[mt][nt][2] + b0, acc[mt][nt][3] + b1);
            *reinterpret_cast<float2*>(C + (size_t)row0 * 1024 + col) = v0;
            *reinterpret_cast<float2*>(C + (size_t)(row0 + 8) * 1024 + col) = v1;
        }
    }
}

// ---------------------------------------------------------------------------
// rna(tf32) conversion pass
// ---------------------------------------------------------------------------
__global__ __launch_bounds__(256) void conv_rna_kernel(
    const float* __restrict__ src, float* __restrict__ dst, int n4)
{
    int i = blockIdx.x * blockDim.x + threadIdx.x;
    if (i >= n4) return;
    float4 v = reinterpret_cast<const float4*>(src)[i];
    v.x = __uint_as_float(f2tf32(v.x));
    v.y = __uint_as_float(f2tf32(v.y));
    v.z = __uint_as_float(f2tf32(v.z));
    v.w = __uint_as_float(f2tf32(v.w));
    reinterpret_cast<float4*>(dst)[i] = v;
}

// ---------------------------------------------------------------------------
// Scan stage 1: per-(b, chunk, n) chunk-end state (read-only pass)
// ---------------------------------------------------------------------------
__global__ __launch_bounds__(256) void scan_ends_kernel(const float* __restrict__ log_A)
{
    int idx = blockIdx.x * blockDim.x + threadIdx.x;
    int n = idx & (N_STATE - 1);
    int c = (idx / N_STATE) & (NCHUNK - 1);
    int b = idx / (N_STATE * NCHUNK);
    if (b >= BATCH) return;

    const float Av = sigmoidf_(log_A[n]);
    size_t base = ((size_t)b * SEQ_T + (size_t)c * CHUNK) * N_STATE + n;
    float h = 0.0f;
#pragma unroll 4
    for (int tt = 0; tt < CHUNK; tt++)
        h = fmaf(Av, h, g_bx[base + (size_t)tt * N_STATE]);
    g_end[((size_t)b * NCHUNK + c) * N_STATE + n] = h;
}

// ---------------------------------------------------------------------------
// Scan stage 2: carry from ends, final inclusive scan; h written rna-rounded
// (it is GEMM2's A operand).
// ---------------------------------------------------------------------------
__global__ __launch_bounds__(256) void scan_apply_kernel(const float* __restrict__ log_A)
{
    int idx = blockIdx.x * blockDim.x + threadIdx.x;
    int n = idx & (N_STATE - 1);
    int c = (idx / N_STATE) & (NCHUNK - 1);
    int b = idx / (N_STATE * NCHUNK);
    if (b >= BATCH) return;

    const float Av = sigmoidf_(log_A[n]);
    float aL = Av;
#pragma unroll
    for (int s = 0; s < 7; s++) aL = aL * aL;

    float E = 0.0f;
    for (int cp = 0; cp < c; cp++)
        E = fmaf(aL, E, g_end[((size_t)b * NCHUNK + cp) * N_STATE + n]);

    size_t base = ((size_t)b * SEQ_T + (size_t)c * CHUNK) * N_STATE + n;
    float h = E;
#pragma unroll 4
    for (int tt = 0; tt < CHUNK; tt++) {
        size_t off = base + (size_t)tt * N_STATE;
        h = fmaf(Av, h, g_bx[off]);
        g_bx[off] = __uint_as_float(f2tf32(h));
    }
}

// ---------------------------------------------------------------------------
// Launch
// ---------------------------------------------------------------------------
extern "C" void kernel_launch(void* const* d_in, const int* in_sizes, int n_in,
                              void* d_out, int out_size)
{
    const float* x    = (const float*)d_in[0];   // [8, 2048, 1024]
    const float* logA = (const float*)d_in[1];   // [1024]
    const float* B_w  = (const float*)d_in[2];   // [1024, 1024] (N, D)
    const float* B_b  = (const float*)d_in[3];   // [1024]
    const float* C_w  = (const float*)d_in[4];   // [1024, 1024] (D, N)
    const float* C_b  = (const float*)d_in[5];   // [1024]
    float* y = (float*)d_out;                    // [8, 2048, 1024]

    float *bx, *xc, *w1, *w2;
    cudaGetSymbolAddress((void**)&bx, g_bx);
    cudaGetSymbolAddress((void**)&xc, g_xc);
    cudaGetSymbolAddress((void**)&w1, g_w1);
    cudaGetSymbolAddress((void**)&w2, g_w2);

    cudaFuncSetAttribute(gemm_tc_tf32, cudaFuncAttributeMaxDynamicSharedMemorySize,
                         SMEM_GEMM_TOTAL);

    // rna-round operands for tf32 MMA
    {
        int n4x = MROWS * D_MODEL / 4;
        conv_rna_kernel<<<n4x / 256, 256>>>(x, xc, n4x);
        int n4w = N_STATE * D_MODEL / 4;
        conv_rna_kernel<<<n4w / 256, 256>>>(B_w, w1, n4w);
        conv_rna_kernel<<<n4w / 256, 256>>>(C_w, w2, n4w);
    }

    // GEMM1: B_x = x @ B_w^T + B_b
    {
        dim3 grid(N_STATE / BN, MROWS / BM);   // (4, 128)
        gemm_tc_tf32<<<grid, NTHREADS, SMEM_GEMM_TOTAL>>>(xc, w1, B_b, bx);
    }

    // Scan (chunked, 2 passes; h written rna-rounded)
    {
        int total = BATCH * NCHUNK * N_STATE;
        scan_ends_kernel<<<total / 256, 256>>>(logA);
        scan_apply_kernel<<<total / 256, 256>>>(logA);
    }

    // GEMM2: y = h @ C_w^T + C_b
    {
        dim3 grid(D_MODEL / BN, MROWS / BM);   // (4, 128)
        gemm_tc_tf32<<<grid, NTHREADS, SMEM_GEMM_TOTAL>>>(bx, w2, C_b, y);
    }
}

// round 11
// speedup vs baseline: 2.5599x; 1.4710x over previous
#include <cuda_runtime.h>
#include <cuda_fp16.h>
#include <math.h>
#include <stdint.h>

// ---------------------------------------------------------------------------
// Problem shape (fixed)
// ---------------------------------------------------------------------------
constexpr int BATCH = 8;
constexpr int SEQ_T = 2048;
constexpr int D_MODEL = 1024;
constexpr int N_STATE = 1024;
constexpr int MROWS = BATCH * SEQ_T;      // 16384
constexpr int KDIM = 1024;
constexpr int CHUNK = 128;
constexpr int NCHUNK = SEQ_T / CHUNK;     // 16

// Scratch (no cudaMalloc allowed)
__device__ float  g_bx[MROWS * N_STATE];                // GEMM1 out (fp32), scan input
__device__ __half g_h16[MROWS * N_STATE];               // h (fp16) = GEMM2 A operand
__device__ __half g_xh[MROWS * D_MODEL];                // fp16(x)
__device__ __half g_w1h[N_STATE * D_MODEL];             // fp16(B_w)
__device__ __half g_w2h[D_MODEL * N_STATE];             // fp16(C_w)
__device__ float  g_end[BATCH * NCHUNK * N_STATE];      // chunk-end states

__device__ __forceinline__ float sigmoidf_(float x) {
    return 1.0f / (1.0f + __expf(-x));
}
__device__ __forceinline__ uint32_t smem_u32(const void* p) {
    uint32_t a;
    asm("{ .reg .u64 t; cvta.to.shared.u64 t, %1; cvt.u32.u64 %0, t; }" : "=r"(a) : "l"(p));
    return a;
}

#define CP_ASYNC16(dst, src) \
    asm volatile("cp.async.cg.shared.global [%0], [%1], 16;" :: "r"(dst), "l"(src))
#define CP_COMMIT() asm volatile("cp.async.commit_group;" ::: "memory")
#define CP_WAIT2()  asm volatile("cp.async.wait_group 2;" ::: "memory")

#define LDSM_X4(r0, r1, r2, r3, addr) \
    asm volatile("ldmatrix.sync.aligned.m8n8.x4.shared.b16 {%0,%1,%2,%3}, [%4];" \
        : "=r"(r0), "=r"(r1), "=r"(r2), "=r"(r3) : "r"(addr))

// ---------------------------------------------------------------------------
// FP16 mma.sync GEMM: C[M,N=1024](fp32) = A[M,K](fp16)*B[N,K](fp16)^T + bias
// CTA tile 128x256x64, 512 threads / 16 warps (warp tile 64x32), 4-stage
// cp.async pipeline. 128B rows (64 fp16) -> same SW128 layout as tf32 version.
// m16n8k16 HMMA: half the instructions / smem bytes / L2 bytes of tf32.
// ---------------------------------------------------------------------------
constexpr int BM = 128, BN = 256, BK = 64;
constexpr int A_BYTES = BM * 128;                 // 16 KB (64 halves/row = 128B)
constexpr int B_BYTES = BN * 128;                 // 32 KB
constexpr int STAGE_BYTES = A_BYTES + B_BYTES;    // 48 KB
constexpr int NSTAGE = 4;
constexpr int SMEM_GEMM_TOTAL = NSTAGE * STAGE_BYTES;  // 192 KB
constexpr int NITER = KDIM / BK;                  // 16
constexpr int NTHREADS = 512;
constexpr int TOTAL_ROWS = BM + BN;               // 384 rows per stage
constexpr int CHUNKS_PER_THREAD = TOTAL_ROWS * 8 / NTHREADS;  // 6

__global__ __launch_bounds__(NTHREADS, 1) void gemm_tc_f16(
    const __half* __restrict__ A, const __half* __restrict__ Bw,
    const float* __restrict__ bias, float* __restrict__ C)
{
    extern __shared__ char smem[];
    const uint32_t sb = smem_u32(smem);
    const int tid = threadIdx.x;
    const int wid = tid >> 5;          // 0..15
    const int lane = tid & 31;
    const int g = lane >> 2;           // 0..7
    const int t = lane & 3;            // 0..3
    const int mBase = blockIdx.y * BM;
    const int nBase = blockIdx.x * BN;
    const int warpM = (wid & 1) * 64;          // 2 warps along M (128)
    const int warpN = (wid >> 1) * 32;         // 8 warps along N (256)

    // ldmatrix lane roles
    const int j = lane >> 3;          // matrix index 0..3
    const int r = lane & 7;           // row within matrix

    // A fragment (m16n8k16): matrices {rows0-7@kc, rows8-15@kc, rows0-7@kc+1,
    // rows8-15@kc+1} -> row=(j&1)*8+r, chunk+= j>>1.
    uint32_t aRow[4], aXor[4];
#pragma unroll
    for (int mt = 0; mt < 4; mt++) {
        int row = warpM + mt * 16 + (j & 1) * 8 + r;
        aRow[mt] = (uint32_t)row * 128u;
        aXor[mt] = (uint32_t)(row & 7) << 4;
    }
    const uint32_t aKj = (uint32_t)(j >> 1);
    // B fragments: x4 covers two n8-tiles x two k-halves:
    // {n0-7@kc, n0-7@kc+1, n8-15@kc, n8-15@kc+1} -> row=(j>>1)*8+r, chunk+= j&1.
    uint32_t bRow[2], bXor[2];
#pragma unroll
    for (int ntp = 0; ntp < 2; ntp++) {
        int row = warpN + ntp * 16 + (j >> 1) * 8 + r;
        bRow[ntp] = (uint32_t)row * 128u;
        bXor[ntp] = (uint32_t)(row & 7) << 4;
    }
    const uint32_t bKj = (uint32_t)(j & 1);

    float acc[4][4][4];
#pragma unroll
    for (int mt = 0; mt < 4; mt++)
#pragma unroll
        for (int nt = 0; nt < 4; nt++)
#pragma unroll
            for (int q = 0; q < 4; q++) acc[mt][nt][q] = 0.0f;

    uint32_t af[4][4];
    uint32_t bf[4][2];

    // ---- producer: fill stage s with K-chunk at k0 (fp16: 16B = 8 halves).
    //      Rows 0..127 = A tile, rows 128..383 = B tile. ----
    auto fill = [&](int s, int k0) {
        uint32_t stBase = sb + (uint32_t)s * STAGE_BYTES;
#pragma unroll
        for (int q = 0; q < CHUNKS_PER_THREAD; q++) {
            int idx = q * NTHREADS + tid;       // 0..3071
            int row = idx >> 3;                 // 0..383
            int col = idx & 7;
            uint32_t off = (uint32_t)row * 128u +
                           (((uint32_t)col << 4) ^ ((uint32_t)(row & 7) << 4));
            const __half* src = (row < BM)
                ? A  + (size_t)(mBase + row) * KDIM + k0 + col * 8
                : Bw + (size_t)(nBase + row - BM) * KDIM + k0 + col * 8;
            CP_ASYNC16(stBase + off, src);
        }
    };

    fill(0, 0);        CP_COMMIT();
    fill(1, BK);       CP_COMMIT();
    fill(2, 2 * BK);   CP_COMMIT();

    int sComp = 0;     // stage computed this iter
    int sFill = 3;     // stage filled this iter (tile i+3)

    for (int i = 0; i < NITER; i++) {
        CP_WAIT2();            // tile i resident (<=2 younger groups pending)
        __syncthreads();       // visibility + stage sFill free

        const uint32_t aBase = sb + (uint32_t)sComp * STAGE_BYTES;
        const uint32_t bBase = aBase + A_BYTES;

        // issue the global prefetch first (overlaps MMA work below)
        int nk = (i + 3) * BK;
        if (nk < KDIM) fill(sFill, nk);
        CP_COMMIT();

#pragma unroll
        for (int ks = 0; ks < 4; ks++) {        // k16 steps: chunks 2ks, 2ks+1
            const uint32_t kc0 = (uint32_t)ks * 2u;
#pragma unroll
            for (int mt = 0; mt < 4; mt++) {
                uint32_t addr = aBase + aRow[mt] + ((((kc0 + aKj) << 4)) ^ aXor[mt]);
                LDSM_X4(af[mt][0], af[mt][1], af[mt][2], af[mt][3], addr);
            }
#pragma unroll
            for (int ntp = 0; ntp < 2; ntp++) {
                uint32_t addr = bBase + bRow[ntp] + ((((kc0 + bKj) << 4)) ^ bXor[ntp]);
                LDSM_X4(bf[2 * ntp][0], bf[2 * ntp][1],
                        bf[2 * ntp + 1][0], bf[2 * ntp + 1][1], addr);
            }
#pragma unroll
            for (int mt = 0; mt < 4; mt++)
#pragma unroll
                for (int nt = 0; nt < 4; nt++) {
                    asm volatile(
                        "mma.sync.aligned.m16n8k16.row.col.f32.f16.f16.f32 "
                        "{%0,%1,%2,%3}, {%4,%5,%6,%7}, {%8,%9}, {%0,%1,%2,%3};"
                        : "+f"(acc[mt][nt][0]), "+f"(acc[mt][nt][1]),
                          "+f"(acc[mt][nt][2]), "+f"(acc[mt][nt][3])
                        : "r"(af[mt][0]), "r"(af[mt][1]),
                          "r"(af[mt][2]), "r"(af[mt][3]),
                          "r"(bf[nt][0]), "r"(bf[nt][1]));
                }
        }

        sComp = (sComp == NSTAGE - 1) ? 0 : sComp + 1;
        sFill = (sFill == NSTAGE - 1) ? 0 : sFill + 1;
    }

    // ---- epilogue: add bias, store fp32 ----
#pragma unroll
    for (int mt = 0; mt < 4; mt++) {
        int row0 = mBase + warpM + mt * 16 + g;
#pragma unroll
        for (int nt = 0; nt < 4; nt++) {
            int col = nBase + warpN + nt * 8 + 2 * t;
            float b0 = bias[col], b1 = bias[col + 1];
            float2 v0 = make_float2(acc[mt][nt][0] + b0, acc[mt][nt][1] + b1);
            float2 v1 = make_float2(acc[mt][nt][2] + b0, acc[mt][nt][3] + b1);
            *reinterpret_cast<float2*>(C + (size_t)row0 * 1024 + col) = v0;
            *reinterpret_cast<float2*>(C + (size_t)(row0 + 8) * 1024 + col) = v1;
        }
    }
}

// ---------------------------------------------------------------------------
// fp32 -> fp16 conversion pass (rn)
// ---------------------------------------------------------------------------
__global__ __launch_bounds__(256) void conv_f16_kernel(
    const float* __restrict__ src, __half* __restrict__ dst, int n4)
{
    int i = blockIdx.x * blockDim.x + threadIdx.x;
    if (i >= n4) return;
    float4 v = reinterpret_cast<const float4*>(src)[i];
    __half2 h01 = __floats2half2_rn(v.x, v.y);
    __half2 h23 = __floats2half2_rn(v.z, v.w);
    uint2 packed;
    packed.x = *reinterpret_cast<uint32_t*>(&h01);
    packed.y = *reinterpret_cast<uint32_t*>(&h23);
    reinterpret_cast<uint2*>(dst)[i] = packed;
}

// ---------------------------------------------------------------------------
// Scan stage 1: per-(b, chunk, n) chunk-end state (read-only pass)
// ---------------------------------------------------------------------------
__global__ __launch_bounds__(256) void scan_ends_kernel(const float* __restrict__ log_A)
{
    int idx = blockIdx.x * blockDim.x + threadIdx.x;
    int n = idx & (N_STATE - 1);
    int c = (idx / N_STATE) & (NCHUNK - 1);
    int b = idx / (N_STATE * NCHUNK);
    if (b >= BATCH) return;

    const float Av = sigmoidf_(log_A[n]);
    size_t base = ((size_t)b * SEQ_T + (size_t)c * CHUNK) * N_STATE + n;
    float h = 0.0f;
#pragma unroll 4
    for (int tt = 0; tt < CHUNK; tt++)
        h = fmaf(Av, h, g_bx[base + (size_t)tt * N_STATE]);
    g_end[((size_t)b * NCHUNK + c) * N_STATE + n] = h;
}

// ---------------------------------------------------------------------------
// Scan stage 2: carry from ends, final inclusive scan in fp32; h emitted as
// fp16 directly (GEMM2's A operand) -- halves the write traffic.
// ---------------------------------------------------------------------------
__global__ __launch_bounds__(256) void scan_apply_kernel(const float* __restrict__ log_A)
{
    int idx = blockIdx.x * blockDim.x + threadIdx.x;
    int n = idx & (N_STATE - 1);
    int c = (idx / N_STATE) & (NCHUNK - 1);
    int b = idx / (N_STATE * NCHUNK);
    if (b >= BATCH) return;

    const float Av = sigmoidf_(log_A[n]);
    float aL = Av;
#pragma unroll
    for (int s = 0; s < 7; s++) aL = aL * aL;

    float E = 0.0f;
    for (int cp = 0; cp < c; cp++)
        E = fmaf(aL, E, g_end[((size_t)b * NCHUNK + cp) * N_STATE + n]);

    size_t base = ((size_t)b * SEQ_T + (size_t)c * CHUNK) * N_STATE + n;
    float h = E;
#pragma unroll 4
    for (int tt = 0; tt < CHUNK; tt++) {
        size_t off = base + (size_t)tt * N_STATE;
        h = fmaf(Av, h, g_bx[off]);
        g_h16[off] = __float2half_rn(h);
    }
}

// ---------------------------------------------------------------------------
// Launch
// ---------------------------------------------------------------------------
extern "C" void kernel_launch(void* const* d_in, const int* in_sizes, int n_in,
                              void* d_out, int out_size)
{
    const float* x    = (const float*)d_in[0];   // [8, 2048, 1024]
    const float* logA = (const float*)d_in[1];   // [1024]
    const float* B_w  = (const float*)d_in[2];   // [1024, 1024] (N, D)
    const float* B_b  = (const float*)d_in[3];   // [1024]
    const float* C_w  = (const float*)d_in[4];   // [1024, 1024] (D, N)
    const float* C_b  = (const float*)d_in[5];   // [1024]
    float* y = (float*)d_out;                    // [8, 2048, 1024]

    float* bx;
    __half *xh, *w1h, *w2h, *h16;
    cudaGetSymbolAddress((void**)&bx, g_bx);
    cudaGetSymbolAddress((void**)&xh, g_xh);
    cudaGetSymbolAddress((void**)&w1h, g_w1h);
    cudaGetSymbolAddress((void**)&w2h, g_w2h);
    cudaGetSymbolAddress((void**)&h16, g_h16);

    cudaFuncSetAttribute(gemm_tc_f16, cudaFuncAttributeMaxDynamicSharedMemorySize,
                         SMEM_GEMM_TOTAL);

    // fp16-round operands for HMMA
    {
        int n4x = MROWS * D_MODEL / 4;
        conv_f16_kernel<<<n4x / 256, 256>>>(x, xh, n4x);
        int n4w = N_STATE * D_MODEL / 4;
        conv_f16_kernel<<<n4w / 256, 256>>>(B_w, w1h, n4w);
        conv_f16_kernel<<<n4w / 256, 256>>>(C_w, w2h, n4w);
    }

    // GEMM1: B_x = x @ B_w^T + B_b   (fp16 in, fp32 out)
    {
        dim3 grid(N_STATE / BN, MROWS / BM);   // (4, 128)
        gemm_tc_f16<<<grid, NTHREADS, SMEM_GEMM_TOTAL>>>(xh, w1h, B_b, bx);
    }

    // Scan (chunked, 2 passes; h emitted fp16)
    {
        int total = BATCH * NCHUNK * N_STATE;
        scan_ends_kernel<<<total / 256, 256>>>(logA);
        scan_apply_kernel<<<total / 256, 256>>>(logA);
    }

    // GEMM2: y = h @ C_w^T + C_b    (fp16 in, fp32 out)
    {
        dim3 grid(D_MODEL / BN, MROWS / BM);   // (4, 128)
        gemm_tc_f16<<<grid, NTHREADS, SMEM_GEMM_TOTAL>>>(h16, w2h, C_b, y);
    }
}

// round 12
// speedup vs baseline: 2.7059x; 1.0570x over previous
#include <cuda_runtime.h>
#include <cuda_fp16.h>
#include <math.h>
#include <stdint.h>

// ---------------------------------------------------------------------------
// Problem shape (fixed)
// ---------------------------------------------------------------------------
constexpr int BATCH = 8;
constexpr int SEQ_T = 2048;
constexpr int D_MODEL = 1024;
constexpr int N_STATE = 1024;
constexpr int MROWS = BATCH * SEQ_T;      // 16384
constexpr int KDIM = 1024;
constexpr int CHUNK = 128;
constexpr int NCHUNK = SEQ_T / CHUNK;     // 16

// Scratch (no cudaMalloc allowed)
__device__ __half g_bxh[MROWS * N_STATE];               // B_x (fp16) -> h (fp16), in place
__device__ __half g_w1h[N_STATE * D_MODEL];             // fp16(B_w)
__device__ __half g_w2h[D_MODEL * N_STATE];             // fp16(C_w)
__device__ float  g_end[BATCH * NCHUNK * N_STATE];      // chunk-end states

__device__ __forceinline__ float sigmoidf_(float x) {
    return 1.0f / (1.0f + __expf(-x));
}
__device__ __forceinline__ uint32_t smem_u32(const void* p) {
    uint32_t a;
    asm("{ .reg .u64 t; cvta.to.shared.u64 t, %1; cvt.u32.u64 %0, t; }" : "=r"(a) : "l"(p));
    return a;
}

#define CP_ASYNC16(dst, src) \
    asm volatile("cp.async.cg.shared.global [%0], [%1], 16;" :: "r"(dst), "l"(src))
#define CP_COMMIT() asm volatile("cp.async.commit_group;" ::: "memory")
#define CP_WAIT2()  asm volatile("cp.async.wait_group 2;" ::: "memory")

#define LDSM_X4(r0, r1, r2, r3, addr) \
    asm volatile("ldmatrix.sync.aligned.m8n8.x4.shared.b16 {%0,%1,%2,%3}, [%4];" \
        : "=r"(r0), "=r"(r1), "=r"(r2), "=r"(r3) : "r"(addr))

// ---------------------------------------------------------------------------
// Shared GEMM geometry: CTA tile 128x256x64 fp16, 512 thr / 16 warps,
// warp tile 64x32 (m16n8k16), 4-stage pipeline, SW128 smem.
// ---------------------------------------------------------------------------
constexpr int BM = 128, BN = 256, BK = 64;
constexpr int A_BYTES = BM * 128;                 // 16 KB (64 halves/row = 128B)
constexpr int B_BYTES = BN * 128;                 // 32 KB
constexpr int STAGE_BYTES = A_BYTES + B_BYTES;    // 48 KB
constexpr int NSTAGE = 4;
constexpr int SMEM_GEMM_TOTAL = NSTAGE * STAGE_BYTES;  // 192 KB
constexpr int NITER = KDIM / BK;                  // 16
constexpr int NTHREADS = 512;

// ---------------------------------------------------------------------------
// MMA mainloop shared by both GEMMs (macro-free: both kernels repeat the
// pattern; FillA differs, epilogue differs).
// ---------------------------------------------------------------------------

// GEMM1: A fp32 (x), B fp16 (w1), OUT fp16 (B_x)
__global__ __launch_bounds__(NTHREADS, 1) void gemm1_a32_o16(
    const float* __restrict__ A, const __half* __restrict__ Bw,
    const float* __restrict__ bias, __half* __restrict__ C)
{
    extern __shared__ char smem[];
    const uint32_t sb = smem_u32(smem);
    const int tid = threadIdx.x;
    const int wid = tid >> 5;
    const int lane = tid & 31;
    const int g = lane >> 2;
    const int t = lane & 3;
    const int mBase = blockIdx.y * BM;
    const int nBase = blockIdx.x * BN;
    const int warpM = (wid & 1) * 64;
    const int warpN = (wid >> 1) * 32;
    const int j = lane >> 3;
    const int r = lane & 7;

    uint32_t aRow[4], aXor[4];
#pragma unroll
    for (int mt = 0; mt < 4; mt++) {
        int row = warpM + mt * 16 + (j & 1) * 8 + r;
        aRow[mt] = (uint32_t)row * 128u;
        aXor[mt] = (uint32_t)(row & 7) << 4;
    }
    const uint32_t aKj = (uint32_t)(j >> 1);
    uint32_t bRow[2], bXor[2];
#pragma unroll
    for (int ntp = 0; ntp < 2; ntp++) {
        int row = warpN + ntp * 16 + (j >> 1) * 8 + r;
        bRow[ntp] = (uint32_t)row * 128u;
        bXor[ntp] = (uint32_t)(row & 7) << 4;
    }
    const uint32_t bKj = (uint32_t)(j & 1);

    float acc[4][4][4];
#pragma unroll
    for (int mt = 0; mt < 4; mt++)
#pragma unroll
        for (int nt = 0; nt < 4; nt++)
#pragma unroll
            for (int q = 0; q < 4; q++) acc[mt][nt][q] = 0.0f;

    uint32_t af[4][4];
    uint32_t bf[4][2];

    // fill: B via cp.async (4 chunks/thread); A via LDG fp32 + cvt + STS fp16
    auto fill = [&](int s, int k0) {
        uint32_t stBase = sb + (uint32_t)s * STAGE_BYTES;
        char* stPtr = smem + (size_t)s * STAGE_BYTES;
        // B tile: 256 rows x 8 chunks = 2048 chunks
#pragma unroll
        for (int q = 0; q < 4; q++) {
            int idx = q * NTHREADS + tid;
            int row = idx >> 3;
            int col = idx & 7;
            uint32_t off = (uint32_t)A_BYTES + (uint32_t)row * 128u +
                           (((uint32_t)col << 4) ^ ((uint32_t)(row & 7) << 4));
            const __half* src = Bw + (size_t)(nBase + row) * KDIM + k0 + col * 8;
            CP_ASYNC16(stBase + off, src);
        }
        // A tile: 128 rows x 8 chunks = 1024 chunks; fp32 -> fp16
#pragma unroll
        for (int q = 0; q < 2; q++) {
            int idx = q * NTHREADS + tid;
            int row = idx >> 3;
            int col = idx & 7;
            const float4* src = reinterpret_cast<const float4*>(
                A + (size_t)(mBase + row) * KDIM + k0 + col * 8);
            float4 v0 = src[0];
            float4 v1 = src[1];
            __half2 h0 = __floats2half2_rn(v0.x, v0.y);
            __half2 h1 = __floats2half2_rn(v0.z, v0.w);
            __half2 h2 = __floats2half2_rn(v1.x, v1.y);
            __half2 h3 = __floats2half2_rn(v1.z, v1.w);
            uint4 pk;
            pk.x = *reinterpret_cast<uint32_t*>(&h0);
            pk.y = *reinterpret_cast<uint32_t*>(&h1);
            pk.z = *reinterpret_cast<uint32_t*>(&h2);
            pk.w = *reinterpret_cast<uint32_t*>(&h3);
            uint32_t off = (uint32_t)row * 128u +
                           (((uint32_t)col << 4) ^ ((uint32_t)(row & 7) << 4));
            *reinterpret_cast<uint4*>(stPtr + off) = pk;
        }
    };

    fill(0, 0);        CP_COMMIT();
    fill(1, BK);       CP_COMMIT();
    fill(2, 2 * BK);   CP_COMMIT();

    int sComp = 0, sFill = 3;
    for (int i = 0; i < NITER; i++) {
        CP_WAIT2();
        __syncthreads();

        const uint32_t aBase = sb + (uint32_t)sComp * STAGE_BYTES;
        const uint32_t bBase = aBase + A_BYTES;

        int nk = (i + 3) * BK;
        if (nk < KDIM) fill(sFill, nk);
        CP_COMMIT();

#pragma unroll
        for (int ks = 0; ks < 4; ks++) {
            const uint32_t kc0 = (uint32_t)ks * 2u;
#pragma unroll
            for (int mt = 0; mt < 4; mt++) {
                uint32_t addr = aBase + aRow[mt] + ((((kc0 + aKj) << 4)) ^ aXor[mt]);
                LDSM_X4(af[mt][0], af[mt][1], af[mt][2], af[mt][3], addr);
            }
#pragma unroll
            for (int ntp = 0; ntp < 2; ntp++) {
                uint32_t addr = bBase + bRow[ntp] + ((((kc0 + bKj) << 4)) ^ bXor[ntp]);
                LDSM_X4(bf[2 * ntp][0], bf[2 * ntp][1],
                        bf[2 * ntp + 1][0], bf[2 * ntp + 1][1], addr);
            }
#pragma unroll
            for (int mt = 0; mt < 4; mt++)
#pragma unroll
                for (int nt = 0; nt < 4; nt++) {
                    asm volatile(
                        "mma.sync.aligned.m16n8k16.row.col.f32.f16.f16.f32 "
                        "{%0,%1,%2,%3}, {%4,%5,%6,%7}, {%8,%9}, {%0,%1,%2,%3};"
                        : "+f"(acc[mt][nt][0]), "+f"(acc[mt][nt][1]),
                          "+f"(acc[mt][nt][2]), "+f"(acc[mt][nt][3])
                        : "r"(af[mt][0]), "r"(af[mt][1]),
                          "r"(af[mt][2]), "r"(af[mt][3]),
                          "r"(bf[nt][0]), "r"(bf[nt][1]));
                }
        }
        sComp = (sComp == NSTAGE - 1) ? 0 : sComp + 1;
        sFill = (sFill == NSTAGE - 1) ? 0 : sFill + 1;
    }

    // epilogue: +bias, store fp16
#pragma unroll
    for (int mt = 0; mt < 4; mt++) {
        int row0 = mBase + warpM + mt * 16 + g;
#pragma unroll
        for (int nt = 0; nt < 4; nt++) {
            int col = nBase + warpN + nt * 8 + 2 * t;
            float b0 = bias[col], b1 = bias[col + 1];
            __half2 v0 = __floats2half2_rn(acc[mt][nt][0] + b0, acc[mt][nt][1] + b1);
            __half2 v1 = __floats2half2_rn(acc[mt][nt][2] + b0, acc[mt][nt][3] + b1);
            *reinterpret_cast<__half2*>(C + (size_t)row0 * 1024 + col) = v0;
            *reinterpret_cast<__half2*>(C + (size_t)(row0 + 8) * 1024 + col) = v1;
        }
    }
}

// GEMM2: A fp16 (h), B fp16 (w2), OUT fp32 (y)
__global__ __launch_bounds__(NTHREADS, 1) void gemm2_a16_o32(
    const __half* __restrict__ A, const __half* __restrict__ Bw,
    const float* __restrict__ bias, float* __restrict__ C)
{
    extern __shared__ char smem[];
    const uint32_t sb = smem_u32(smem);
    const int tid = threadIdx.x;
    const int wid = tid >> 5;
    const int lane = tid & 31;
    const int g = lane >> 2;
    const int t = lane & 3;
    const int mBase = blockIdx.y * BM;
    const int nBase = blockIdx.x * BN;
    const int warpM = (wid & 1) * 64;
    const int warpN = (wid >> 1) * 32;
    const int j = lane >> 3;
    const int r = lane & 7;

    uint32_t aRow[4], aXor[4];
#pragma unroll
    for (int mt = 0; mt < 4; mt++) {
        int row = warpM + mt * 16 + (j & 1) * 8 + r;
        aRow[mt] = (uint32_t)row * 128u;
        aXor[mt] = (uint32_t)(row & 7) << 4;
    }
    const uint32_t aKj = (uint32_t)(j >> 1);
    uint32_t bRow[2], bXor[2];
#pragma unroll
    for (int ntp = 0; ntp < 2; ntp++) {
        int row = warpN + ntp * 16 + (j >> 1) * 8 + r;
        bRow[ntp] = (uint32_t)row * 128u;
        bXor[ntp] = (uint32_t)(row & 7) << 4;
    }
    const uint32_t bKj = (uint32_t)(j & 1);

    float acc[4][4][4];
#pragma unroll
    for (int mt = 0; mt < 4; mt++)
#pragma unroll
        for (int nt = 0; nt < 4; nt++)
#pragma unroll
            for (int q = 0; q < 4; q++) acc[mt][nt][q] = 0.0f;

    uint32_t af[4][4];
    uint32_t bf[4][2];

    auto fill = [&](int s, int k0) {
        uint32_t stBase = sb + (uint32_t)s * STAGE_BYTES;
#pragma unroll
        for (int q = 0; q < 6; q++) {
            int idx = q * NTHREADS + tid;       // 0..3071
            int row = idx >> 3;                 // 0..383
            int col = idx & 7;
            uint32_t off = (uint32_t)row * 128u +
                           (((uint32_t)col << 4) ^ ((uint32_t)(row & 7) << 4));
            const __half* src = (row < BM)
                ? A  + (size_t)(mBase + row) * KDIM + k0 + col * 8
                : Bw + (size_t)(nBase + row - BM) * KDIM + k0 + col * 8;
            CP_ASYNC16(stBase + off, src);
        }
    };

    fill(0, 0);        CP_COMMIT();
    fill(1, BK);       CP_COMMIT();
    fill(2, 2 * BK);   CP_COMMIT();

    int sComp = 0, sFill = 3;
    for (int i = 0; i < NITER; i++) {
        CP_WAIT2();
        __syncthreads();

        const uint32_t aBase = sb + (uint32_t)sComp * STAGE_BYTES;
        const uint32_t bBase = aBase + A_BYTES;

        int nk = (i + 3) * BK;
        if (nk < KDIM) fill(sFill, nk);
        CP_COMMIT();

#pragma unroll
        for (int ks = 0; ks < 4; ks++) {
            const uint32_t kc0 = (uint32_t)ks * 2u;
#pragma unroll
            for (int mt = 0; mt < 4; mt++) {
                uint32_t addr = aBase + aRow[mt] + ((((kc0 + aKj) << 4)) ^ aXor[mt]);
                LDSM_X4(af[mt][0], af[mt][1], af[mt][2], af[mt][3], addr);
            }
#pragma unroll
            for (int ntp = 0; ntp < 2; ntp++) {
                uint32_t addr = bBase + bRow[ntp] + ((((kc0 + bKj) << 4)) ^ bXor[ntp]);
                LDSM_X4(bf[2 * ntp][0], bf[2 * ntp][1],
                        bf[2 * ntp + 1][0], bf[2 * ntp + 1][1], addr);
            }
#pragma unroll
            for (int mt = 0; mt < 4; mt++)
#pragma unroll
                for (int nt = 0; nt < 4; nt++) {
                    asm volatile(
                        "mma.sync.aligned.m16n8k16.row.col.f32.f16.f16.f32 "
                        "{%0,%1,%2,%3}, {%4,%5,%6,%7}, {%8,%9}, {%0,%1,%2,%3};"
                        : "+f"(acc[mt][nt][0]), "+f"(acc[mt][nt][1]),
                          "+f"(acc[mt][nt][2]), "+f"(acc[mt][nt][3])
                        : "r"(af[mt][0]), "r"(af[mt][1]),
                          "r"(af[mt][2]), "r"(af[mt][3]),
                          "r"(bf[nt][0]), "r"(bf[nt][1]));
                }
        }
        sComp = (sComp == NSTAGE - 1) ? 0 : sComp + 1;
        sFill = (sFill == NSTAGE - 1) ? 0 : sFill + 1;
    }

#pragma unroll
    for (int mt = 0; mt < 4; mt++) {
        int row0 = mBase + warpM + mt * 16 + g;
#pragma unroll
        for (int nt = 0; nt < 4; nt++) {
            int col = nBase + warpN + nt * 8 + 2 * t;
            float b0 = bias[col], b1 = bias[col + 1];
            float2 v0 = make_float2(acc[mt][nt][0] + b0, acc[mt][nt][1] + b1);
            float2 v1 = make_float2(acc[mt][nt][2] + b0, acc[mt][nt][3] + b1);
            *reinterpret_cast<float2*>(C + (size_t)row0 * 1024 + col) = v0;
            *reinterpret_cast<float2*>(C + (size_t)(row0 + 8) * 1024 + col) = v1;
        }
    }
}

// ---------------------------------------------------------------------------
// fp32 -> fp16 conversion pass (weights only)
// ---------------------------------------------------------------------------
__global__ __launch_bounds__(256) void conv_f16_kernel(
    const float* __restrict__ src, __half* __restrict__ dst, int n4)
{
    int i = blockIdx.x * blockDim.x + threadIdx.x;
    if (i >= n4) return;
    float4 v = reinterpret_cast<const float4*>(src)[i];
    __half2 h01 = __floats2half2_rn(v.x, v.y);
    __half2 h23 = __floats2half2_rn(v.z, v.w);
    uint2 packed;
    packed.x = *reinterpret_cast<uint32_t*>(&h01);
    packed.y = *reinterpret_cast<uint32_t*>(&h23);
    reinterpret_cast<uint2*>(dst)[i] = packed;
}

// ---------------------------------------------------------------------------
// Scan stage 1: chunk-end states from fp16 B_x (fp32 accumulation)
// ---------------------------------------------------------------------------
__global__ __launch_bounds__(256) void scan_ends_kernel(const float* __restrict__ log_A)
{
    int idx = blockIdx.x * blockDim.x + threadIdx.x;
    int n = idx & (N_STATE - 1);
    int c = (idx / N_STATE) & (NCHUNK - 1);
    int b = idx / (N_STATE * NCHUNK);
    if (b >= BATCH) return;

    const float Av = sigmoidf_(log_A[n]);
    size_t base = ((size_t)b * SEQ_T + (size_t)c * CHUNK) * N_STATE + n;
    float h = 0.0f;
#pragma unroll 4
    for (int tt = 0; tt < CHUNK; tt++)
        h = fmaf(Av, h, __half2float(g_bxh[base + (size_t)tt * N_STATE]));
    g_end[((size_t)b * NCHUNK + c) * N_STATE + n] = h;
}

// ---------------------------------------------------------------------------
// Scan stage 2: carry from ends, inclusive scan, write h fp16 IN PLACE
// ---------------------------------------------------------------------------
__global__ __launch_bounds__(256) void scan_apply_kernel(const float* __restrict__ log_A)
{
    int idx = blockIdx.x * blockDim.x + threadIdx.x;
    int n = idx & (N_STATE - 1);
    int c = (idx / N_STATE) & (NCHUNK - 1);
    int b = idx / (N_STATE * NCHUNK);
    if (b >= BATCH) return;

    const float Av = sigmoidf_(log_A[n]);
    float aL = Av;
#pragma unroll
    for (int s = 0; s < 7; s++) aL = aL * aL;

    float E = 0.0f;
    for (int cp = 0; cp < c; cp++)
        E = fmaf(aL, E, g_end[((size_t)b * NCHUNK + cp) * N_STATE + n]);

    size_t base = ((size_t)b * SEQ_T + (size_t)c * CHUNK) * N_STATE + n;
    float h = E;
#pragma unroll 4
    for (int tt = 0; tt < CHUNK; tt++) {
        size_t off = base + (size_t)tt * N_STATE;
        h = fmaf(Av, h, __half2float(g_bxh[off]));
        g_bxh[off] = __float2half_rn(h);
    }
}

// ---------------------------------------------------------------------------
// Launch
// ---------------------------------------------------------------------------
extern "C" void kernel_launch(void* const* d_in, const int* in_sizes, int n_in,
                              void* d_out, int out_size)
{
    const float* x    = (const float*)d_in[0];   // [8, 2048, 1024]
    const float* logA = (const float*)d_in[1];   // [1024]
    const float* B_w  = (const float*)d_in[2];   // [1024, 1024] (N, D)
    const float* B_b  = (const float*)d_in[3];   // [1024]
    const float* C_w  = (const float*)d_in[4];   // [1024, 1024] (D, N)
    const float* C_b  = (const float*)d_in[5];   // [1024]
    float* y = (float*)d_out;                    // [8, 2048, 1024]

    __half *bxh, *w1h, *w2h;
    cudaGetSymbolAddress((void**)&bxh, g_bxh);
    cudaGetSymbolAddress((void**)&w1h, g_w1h);
    cudaGetSymbolAddress((void**)&w2h, g_w2h);

    cudaFuncSetAttribute(gemm1_a32_o16, cudaFuncAttributeMaxDynamicSharedMemorySize,
                         SMEM_GEMM_TOTAL);
    cudaFuncSetAttribute(gemm2_a16_o32, cudaFuncAttributeMaxDynamicSharedMemorySize,
                         SMEM_GEMM_TOTAL);

    // fp16 weights (tiny passes)
    {
        int n4w = N_STATE * D_MODEL / 4;
        conv_f16_kernel<<<n4w / 256, 256>>>(B_w, w1h, n4w);
        conv_f16_kernel<<<n4w / 256, 256>>>(C_w, w2h, n4w);
    }

    // GEMM1: B_x(fp16) = x(fp32) @ B_w^T + B_b
    {
        dim3 grid(N_STATE / BN, MROWS / BM);   // (4, 128)
        gemm1_a32_o16<<<grid, NTHREADS, SMEM_GEMM_TOTAL>>>(x, w1h, B_b, bxh);
    }

    // Scan (2 passes on fp16 buffer, fp32 accumulation, in-place h)
    {
        int total = BATCH * NCHUNK * N_STATE;
        scan_ends_kernel<<<total / 256, 256>>>(logA);
        scan_apply_kernel<<<total / 256, 256>>>(logA);
    }

    // GEMM2: y(fp32) = h(fp16) @ C_w^T + C_b
    {
        dim3 grid(D_MODEL / BN, MROWS / BM);   // (4, 128)
        gemm2_a16_o32<<<grid, NTHREADS, SMEM_GEMM_TOTAL>>>(bxh, w2h, C_b, y);
    }
}

// round 13
// speedup vs baseline: 2.7653x; 1.0220x over previous
#include <cuda_runtime.h>
#include <cuda_fp16.h>
#include <math.h>
#include <stdint.h>

// ---------------------------------------------------------------------------
// Problem shape (fixed)
// ---------------------------------------------------------------------------
constexpr int BATCH = 8;
constexpr int SEQ_T = 2048;
constexpr int D_MODEL = 1024;
constexpr int N_STATE = 1024;
constexpr int MROWS = BATCH * SEQ_T;      // 16384
constexpr int KDIM = 1024;
constexpr int CHUNK = 128;
constexpr int NCHUNK = SEQ_T / CHUNK;     // 16

// Scratch (no cudaMalloc allowed)
__device__ __half g_bxh[MROWS * N_STATE];               // B_x (fp16) -> h (fp16), in place
__device__ __half g_w1h[N_STATE * D_MODEL];             // fp16(B_w)
__device__ __half g_w2h[D_MODEL * N_STATE];             // fp16(C_w)
__device__ float  g_end[BATCH * NCHUNK * N_STATE];      // chunk-end states

__device__ __forceinline__ float sigmoidf_(float x) {
    return 1.0f / (1.0f + __expf(-x));
}
__device__ __forceinline__ uint32_t smem_u32(const void* p) {
    uint32_t a;
    asm("{ .reg .u64 t; cvta.to.shared.u64 t, %1; cvt.u32.u64 %0, t; }" : "=r"(a) : "l"(p));
    return a;
}

#define CP_ASYNC16(dst, src) \
    asm volatile("cp.async.cg.shared.global [%0], [%1], 16;" :: "r"(dst), "l"(src))
#define CP_COMMIT() asm volatile("cp.async.commit_group;" ::: "memory")
#define CP_WAIT2()  asm volatile("cp.async.wait_group 2;" ::: "memory")

#define LDSM_X4(r0, r1, r2, r3, addr) \
    asm volatile("ldmatrix.sync.aligned.m8n8.x4.shared.b16 {%0,%1,%2,%3}, [%4];" \
        : "=r"(r0), "=r"(r1), "=r"(r2), "=r"(r3) : "r"(addr))

// ---------------------------------------------------------------------------
// Shared GEMM geometry: CTA tile 128x256x64 fp16, 512 thr / 16 warps,
// warp tile 64x32 (m16n8k16), 4-stage pipeline, SW128 smem.
// ---------------------------------------------------------------------------
constexpr int BM = 128, BN = 256, BK = 64;
constexpr int A_BYTES = BM * 128;                 // 16 KB (64 halves/row = 128B)
constexpr int B_BYTES = BN * 128;                 // 32 KB
constexpr int STAGE_BYTES = A_BYTES + B_BYTES;    // 48 KB
constexpr int NSTAGE = 4;
constexpr int SMEM_GEMM_TOTAL = NSTAGE * STAGE_BYTES;  // 192 KB
constexpr int NITER = KDIM / BK;                  // 16
constexpr int NTHREADS = 512;

// GEMM1: A fp32 (x), B fp16 (w1), OUT fp16 (B_x)
__global__ __launch_bounds__(NTHREADS, 1) void gemm1_a32_o16(
    const float* __restrict__ A, const __half* __restrict__ Bw,
    const float* __restrict__ bias, __half* __restrict__ C)
{
    extern __shared__ char smem[];
    const uint32_t sb = smem_u32(smem);
    const int tid = threadIdx.x;
    const int wid = tid >> 5;
    const int lane = tid & 31;
    const int g = lane >> 2;
    const int t = lane & 3;
    const int mBase = blockIdx.y * BM;
    const int nBase = blockIdx.x * BN;
    const int warpM = (wid & 1) * 64;
    const int warpN = (wid >> 1) * 32;
    const int j = lane >> 3;
    const int r = lane & 7;

    uint32_t aRow[4], aXor[4];
#pragma unroll
    for (int mt = 0; mt < 4; mt++) {
        int row = warpM + mt * 16 + (j & 1) * 8 + r;
        aRow[mt] = (uint32_t)row * 128u;
        aXor[mt] = (uint32_t)(row & 7) << 4;
    }
    const uint32_t aKj = (uint32_t)(j >> 1);
    uint32_t bRow[2], bXor[2];
#pragma unroll
    for (int ntp = 0; ntp < 2; ntp++) {
        int row = warpN + ntp * 16 + (j >> 1) * 8 + r;
        bRow[ntp] = (uint32_t)row * 128u;
        bXor[ntp] = (uint32_t)(row & 7) << 4;
    }
    const uint32_t bKj = (uint32_t)(j & 1);

    float acc[4][4][4];
#pragma unroll
    for (int mt = 0; mt < 4; mt++)
#pragma unroll
        for (int nt = 0; nt < 4; nt++)
#pragma unroll
            for (int q = 0; q < 4; q++) acc[mt][nt][q] = 0.0f;

    uint32_t af[4][4];
    uint32_t bf[4][2];

    // fill: B via cp.async (4 chunks/thread); A via LDG fp32 + cvt + STS fp16
    auto fill = [&](int s, int k0) {
        uint32_t stBase = sb + (uint32_t)s * STAGE_BYTES;
        char* stPtr = smem + (size_t)s * STAGE_BYTES;
#pragma unroll
        for (int q = 0; q < 4; q++) {
            int idx = q * NTHREADS + tid;
            int row = idx >> 3;
            int col = idx & 7;
            uint32_t off = (uint32_t)A_BYTES + (uint32_t)row * 128u +
                           (((uint32_t)col << 4) ^ ((uint32_t)(row & 7) << 4));
            const __half* src = Bw + (size_t)(nBase + row) * KDIM + k0 + col * 8;
            CP_ASYNC16(stBase + off, src);
        }
#pragma unroll
        for (int q = 0; q < 2; q++) {
            int idx = q * NTHREADS + tid;
            int row = idx >> 3;
            int col = idx & 7;
            const float4* src = reinterpret_cast<const float4*>(
                A + (size_t)(mBase + row) * KDIM + k0 + col * 8);
            float4 v0 = src[0];
            float4 v1 = src[1];
            __half2 h0 = __floats2half2_rn(v0.x, v0.y);
            __half2 h1 = __floats2half2_rn(v0.z, v0.w);
            __half2 h2 = __floats2half2_rn(v1.x, v1.y);
            __half2 h3 = __floats2half2_rn(v1.z, v1.w);
            uint4 pk;
            pk.x = *reinterpret_cast<uint32_t*>(&h0);
            pk.y = *reinterpret_cast<uint32_t*>(&h1);
            pk.z = *reinterpret_cast<uint32_t*>(&h2);
            pk.w = *reinterpret_cast<uint32_t*>(&h3);
            uint32_t off = (uint32_t)row * 128u +
                           (((uint32_t)col << 4) ^ ((uint32_t)(row & 7) << 4));
            *reinterpret_cast<uint4*>(stPtr + off) = pk;
        }
    };

    fill(0, 0);        CP_COMMIT();
    fill(1, BK);       CP_COMMIT();
    fill(2, 2 * BK);   CP_COMMIT();

    int sComp = 0, sFill = 3;
    for (int i = 0; i < NITER; i++) {
        CP_WAIT2();
        __syncthreads();

        const uint32_t aBase = sb + (uint32_t)sComp * STAGE_BYTES;
        const uint32_t bBase = aBase + A_BYTES;

        int nk = (i + 3) * BK;
        if (nk < KDIM) fill(sFill, nk);
        CP_COMMIT();

#pragma unroll
        for (int ks = 0; ks < 4; ks++) {
            const uint32_t kc0 = (uint32_t)ks * 2u;
#pragma unroll
            for (int mt = 0; mt < 4; mt++) {
                uint32_t addr = aBase + aRow[mt] + ((((kc0 + aKj) << 4)) ^ aXor[mt]);
                LDSM_X4(af[mt][0], af[mt][1], af[mt][2], af[mt][3], addr);
            }
#pragma unroll
            for (int ntp = 0; ntp < 2; ntp++) {
                uint32_t addr = bBase + bRow[ntp] + ((((kc0 + bKj) << 4)) ^ bXor[ntp]);
                LDSM_X4(bf[2 * ntp][0], bf[2 * ntp][1],
                        bf[2 * ntp + 1][0], bf[2 * ntp + 1][1], addr);
            }
#pragma unroll
            for (int mt = 0; mt < 4; mt++)
#pragma unroll
                for (int nt = 0; nt < 4; nt++) {
                    asm volatile(
                        "mma.sync.aligned.m16n8k16.row.col.f32.f16.f16.f32 "
                        "{%0,%1,%2,%3}, {%4,%5,%6,%7}, {%8,%9}, {%0,%1,%2,%3};"
                        : "+f"(acc[mt][nt][0]), "+f"(acc[mt][nt][1]),
                          "+f"(acc[mt][nt][2]), "+f"(acc[mt][nt][3])
                        : "r"(af[mt][0]), "r"(af[mt][1]),
                          "r"(af[mt][2]), "r"(af[mt][3]),
                          "r"(bf[nt][0]), "r"(bf[nt][1]));
                }
        }
        sComp = (sComp == NSTAGE - 1) ? 0 : sComp + 1;
        sFill = (sFill == NSTAGE - 1) ? 0 : sFill + 1;
    }

#pragma unroll
    for (int mt = 0; mt < 4; mt++) {
        int row0 = mBase + warpM + mt * 16 + g;
#pragma unroll
        for (int nt = 0; nt < 4; nt++) {
            int col = nBase + warpN + nt * 8 + 2 * t;
            float b0 = bias[col], b1 = bias[col + 1];
            __half2 v0 = __floats2half2_rn(acc[mt][nt][0] + b0, acc[mt][nt][1] + b1);
            __half2 v1 = __floats2half2_rn(acc[mt][nt][2] + b0, acc[mt][nt][3] + b1);
            *reinterpret_cast<__half2*>(C + (size_t)row0 * 1024 + col) = v0;
            *reinterpret_cast<__half2*>(C + (size_t)(row0 + 8) * 1024 + col) = v1;
        }
    }
}

// GEMM2: A fp16 (h), B fp16 (w2), OUT fp32 (y)
__global__ __launch_bounds__(NTHREADS, 1) void gemm2_a16_o32(
    const __half* __restrict__ A, const __half* __restrict__ Bw,
    const float* __restrict__ bias, float* __restrict__ C)
{
    extern __shared__ char smem[];
    const uint32_t sb = smem_u32(smem);
    const int tid = threadIdx.x;
    const int wid = tid >> 5;
    const int lane = tid & 31;
    const int g = lane >> 2;
    const int t = lane & 3;
    const int mBase = blockIdx.y * BM;
    const int nBase = blockIdx.x * BN;
    const int warpM = (wid & 1) * 64;
    const int warpN = (wid >> 1) * 32;
    const int j = lane >> 3;
    const int r = lane & 7;

    uint32_t aRow[4], aXor[4];
#pragma unroll
    for (int mt = 0; mt < 4; mt++) {
        int row = warpM + mt * 16 + (j & 1) * 8 + r;
        aRow[mt] = (uint32_t)row * 128u;
        aXor[mt] = (uint32_t)(row & 7) << 4;
    }
    const uint32_t aKj = (uint32_t)(j >> 1);
    uint32_t bRow[2], bXor[2];
#pragma unroll
    for (int ntp = 0; ntp < 2; ntp++) {
        int row = warpN + ntp * 16 + (j >> 1) * 8 + r;
        bRow[ntp] = (uint32_t)row * 128u;
        bXor[ntp] = (uint32_t)(row & 7) << 4;
    }
    const uint32_t bKj = (uint32_t)(j & 1);

    float acc[4][4][4];
#pragma unroll
    for (int mt = 0; mt < 4; mt++)
#pragma unroll
        for (int nt = 0; nt < 4; nt++)
#pragma unroll
            for (int q = 0; q < 4; q++) acc[mt][nt][q] = 0.0f;

    uint32_t af[4][4];
    uint32_t bf[4][2];

    auto fill = [&](int s, int k0) {
        uint32_t stBase = sb + (uint32_t)s * STAGE_BYTES;
#pragma unroll
        for (int q = 0; q < 6; q++) {
            int idx = q * NTHREADS + tid;       // 0..3071
            int row = idx >> 3;                 // 0..383
            int col = idx & 7;
            uint32_t off = (uint32_t)row * 128u +
                           (((uint32_t)col << 4) ^ ((uint32_t)(row & 7) << 4));
            const __half* src = (row < BM)
                ? A  + (size_t)(mBase + row) * KDIM + k0 + col * 8
                : Bw + (size_t)(nBase + row - BM) * KDIM + k0 + col * 8;
            CP_ASYNC16(stBase + off, src);
        }
    };

    fill(0, 0);        CP_COMMIT();
    fill(1, BK);       CP_COMMIT();
    fill(2, 2 * BK);   CP_COMMIT();

    int sComp = 0, sFill = 3;
    for (int i = 0; i < NITER; i++) {
        CP_WAIT2();
        __syncthreads();

        const uint32_t aBase = sb + (uint32_t)sComp * STAGE_BYTES;
        const uint32_t bBase = aBase + A_BYTES;

        int nk = (i + 3) * BK;
        if (nk < KDIM) fill(sFill, nk);
        CP_COMMIT();

#pragma unroll
        for (int ks = 0; ks < 4; ks++) {
            const uint32_t kc0 = (uint32_t)ks * 2u;
#pragma unroll
            for (int mt = 0; mt < 4; mt++) {
                uint32_t addr = aBase + aRow[mt] + ((((kc0 + aKj) << 4)) ^ aXor[mt]);
                LDSM_X4(af[mt][0], af[mt][1], af[mt][2], af[mt][3], addr);
            }
#pragma unroll
            for (int ntp = 0; ntp < 2; ntp++) {
                uint32_t addr = bBase + bRow[ntp] + ((((kc0 + bKj) << 4)) ^ bXor[ntp]);
                LDSM_X4(bf[2 * ntp][0], bf[2 * ntp][1],
                        bf[2 * ntp + 1][0], bf[2 * ntp + 1][1], addr);
            }
#pragma unroll
            for (int mt = 0; mt < 4; mt++)
#pragma unroll
                for (int nt = 0; nt < 4; nt++) {
                    asm volatile(
                        "mma.sync.aligned.m16n8k16.row.col.f32.f16.f16.f32 "
                        "{%0,%1,%2,%3}, {%4,%5,%6,%7}, {%8,%9}, {%0,%1,%2,%3};"
                        : "+f"(acc[mt][nt][0]), "+f"(acc[mt][nt][1]),
                          "+f"(acc[mt][nt][2]), "+f"(acc[mt][nt][3])
                        : "r"(af[mt][0]), "r"(af[mt][1]),
                          "r"(af[mt][2]), "r"(af[mt][3]),
                          "r"(bf[nt][0]), "r"(bf[nt][1]));
                }
        }
        sComp = (sComp == NSTAGE - 1) ? 0 : sComp + 1;
        sFill = (sFill == NSTAGE - 1) ? 0 : sFill + 1;
    }

#pragma unroll
    for (int mt = 0; mt < 4; mt++) {
        int row0 = mBase + warpM + mt * 16 + g;
#pragma unroll
        for (int nt = 0; nt < 4; nt++) {
            int col = nBase + warpN + nt * 8 + 2 * t;
            float b0 = bias[col], b1 = bias[col + 1];
            float2 v0 = make_float2(acc[mt][nt][0] + b0, acc[mt][nt][1] + b1);
            float2 v1 = make_float2(acc[mt][nt][2] + b0, acc[mt][nt][3] + b1);
            *reinterpret_cast<float2*>(C + (size_t)row0 * 1024 + col) = v0;
            *reinterpret_cast<float2*>(C + (size_t)(row0 + 8) * 1024 + col) = v1;
        }
    }
}

// ---------------------------------------------------------------------------
// Fused weight conversion: both B_w and C_w in one launch
// ---------------------------------------------------------------------------
constexpr int W_N4 = N_STATE * D_MODEL / 4;       // 262144 float4 per weight

__global__ __launch_bounds__(256) void conv_w_kernel(
    const float* __restrict__ w1, const float* __restrict__ w2)
{
    int i = blockIdx.x * blockDim.x + threadIdx.x;
    const float* src = (i < W_N4) ? w1 : w2;
    __half* dst = (i < W_N4) ? g_w1h : g_w2h;
    int k = (i < W_N4) ? i : i - W_N4;
    float4 v = reinterpret_cast<const float4*>(src)[k];
    __half2 h01 = __floats2half2_rn(v.x, v.y);
    __half2 h23 = __floats2half2_rn(v.z, v.w);
    uint2 packed;
    packed.x = *reinterpret_cast<uint32_t*>(&h01);
    packed.y = *reinterpret_cast<uint32_t*>(&h23);
    reinterpret_cast<uint2*>(dst)[k] = packed;
}

// ---------------------------------------------------------------------------
// Scan stage 1 (vectorized x4): chunk-end states from fp16 B_x
// Each thread owns 4 consecutive states (uint2 loads, 4 indep FMA chains).
// ---------------------------------------------------------------------------
constexpr int N4 = N_STATE / 4;                   // 256

__global__ __launch_bounds__(256) void scan_ends_kernel(const float* __restrict__ log_A)
{
    int idx = blockIdx.x * blockDim.x + threadIdx.x;   // B*NCHUNK*N4
    int n4 = idx & (N4 - 1);
    int c = (idx / N4) & (NCHUNK - 1);
    int b = idx / (N4 * NCHUNK);
    if (b >= BATCH) return;

    float4 la = reinterpret_cast<const float4*>(log_A)[n4];
    float A0 = sigmoidf_(la.x), A1 = sigmoidf_(la.y);
    float A2 = sigmoidf_(la.z), A3 = sigmoidf_(la.w);

    const uint2* src = reinterpret_cast<const uint2*>(
        g_bxh + ((size_t)b * SEQ_T + (size_t)c * CHUNK) * N_STATE) + n4;
    float h0 = 0.f, h1 = 0.f, h2 = 0.f, h3 = 0.f;
#pragma unroll 8
    for (int tt = 0; tt < CHUNK; tt++) {
        uint2 v = src[(size_t)tt * N4];
        __half2 p0 = *reinterpret_cast<__half2*>(&v.x);
        __half2 p1 = *reinterpret_cast<__half2*>(&v.y);
        float2 f0 = __half22float2(p0);
        float2 f1 = __half22float2(p1);
        h0 = fmaf(A0, h0, f0.x);
        h1 = fmaf(A1, h1, f0.y);
        h2 = fmaf(A2, h2, f1.x);
        h3 = fmaf(A3, h3, f1.y);
    }
    float4 e = make_float4(h0, h1, h2, h3);
    reinterpret_cast<float4*>(g_end + ((size_t)b * NCHUNK + c) * N_STATE)[n4] = e;
}

// ---------------------------------------------------------------------------
// Scan stage 2 (vectorized x4): carry + inclusive scan, fp16 h in place
// ---------------------------------------------------------------------------
__global__ __launch_bounds__(256) void scan_apply_kernel(const float* __restrict__ log_A)
{
    int idx = blockIdx.x * blockDim.x + threadIdx.x;
    int n4 = idx & (N4 - 1);
    int c = (idx / N4) & (NCHUNK - 1);
    int b = idx / (N4 * NCHUNK);
    if (b >= BATCH) return;

    float4 la = reinterpret_cast<const float4*>(log_A)[n4];
    float A0 = sigmoidf_(la.x), A1 = sigmoidf_(la.y);
    float A2 = sigmoidf_(la.z), A3 = sigmoidf_(la.w);

    float aL0 = A0, aL1 = A1, aL2 = A2, aL3 = A3;   // A^128
#pragma unroll
    for (int s = 0; s < 7; s++) {
        aL0 *= aL0; aL1 *= aL1; aL2 *= aL2; aL3 *= aL3;
    }

    float E0 = 0.f, E1 = 0.f, E2 = 0.f, E3 = 0.f;
    for (int cp = 0; cp < c; cp++) {
        float4 e = reinterpret_cast<const float4*>(
            g_end + ((size_t)b * NCHUNK + cp) * N_STATE)[n4];
        E0 = fmaf(aL0, E0, e.x);
        E1 = fmaf(aL1, E1, e.y);
        E2 = fmaf(aL2, E2, e.z);
        E3 = fmaf(aL3, E3, e.w);
    }

    uint2* buf = reinterpret_cast<uint2*>(
        g_bxh + ((size_t)b * SEQ_T + (size_t)c * CHUNK) * N_STATE) + n4;
    float h0 = E0, h1 = E1, h2 = E2, h3 = E3;
#pragma unroll 8
    for (int tt = 0; tt < CHUNK; tt++) {
        uint2 v = buf[(size_t)tt * N4];
        __half2 p0 = *reinterpret_cast<__half2*>(&v.x);
        __half2 p1 = *reinterpret_cast<__half2*>(&v.y);
        float2 f0 = __half22float2(p0);
        float2 f1 = __half22float2(p1);
        h0 = fmaf(A0, h0, f0.x);
        h1 = fmaf(A1, h1, f0.y);
        h2 = fmaf(A2, h2, f1.x);
        h3 = fmaf(A3, h3, f1.y);
        __half2 o0 = __floats2half2_rn(h0, h1);
        __half2 o1 = __floats2half2_rn(h2, h3);
        uint2 ov;
        ov.x = *reinterpret_cast<uint32_t*>(&o0);
        ov.y = *reinterpret_cast<uint32_t*>(&o1);
        buf[(size_t)tt * N4] = ov;
    }
}

// ---------------------------------------------------------------------------
// Launch
// ---------------------------------------------------------------------------
extern "C" void kernel_launch(void* const* d_in, const int* in_sizes, int n_in,
                              void* d_out, int out_size)
{
    const float* x    = (const float*)d_in[0];   // [8, 2048, 1024]
    const float* logA = (const float*)d_in[1];   // [1024]
    const float* B_w  = (const float*)d_in[2];   // [1024, 1024] (N, D)
    const float* B_b  = (const float*)d_in[3];   // [1024]
    const float* C_w  = (const float*)d_in[4];   // [1024, 1024] (D, N)
    const float* C_b  = (const float*)d_in[5];   // [1024]
    float* y = (float*)d_out;                    // [8, 2048, 1024]

    __half *bxh, *w1h, *w2h;
    cudaGetSymbolAddress((void**)&bxh, g_bxh);
    cudaGetSymbolAddress((void**)&w1h, g_w1h);
    cudaGetSymbolAddress((void**)&w2h, g_w2h);

    cudaFuncSetAttribute(gemm1_a32_o16, cudaFuncAttributeMaxDynamicSharedMemorySize,
                         SMEM_GEMM_TOTAL);
    cudaFuncSetAttribute(gemm2_a16_o32, cudaFuncAttributeMaxDynamicSharedMemorySize,
                         SMEM_GEMM_TOTAL);

    // fp16 weights (single fused pass)
    conv_w_kernel<<<2 * W_N4 / 256, 256>>>(B_w, C_w);

    // GEMM1: B_x(fp16) = x(fp32) @ B_w^T + B_b
    {
        dim3 grid(N_STATE / BN, MROWS / BM);   // (4, 128)
        gemm1_a32_o16<<<grid, NTHREADS, SMEM_GEMM_TOTAL>>>(x, w1h, B_b, bxh);
    }

    // Scan (2 vectorized passes on fp16 buffer, fp32 accumulation, in-place h)
    {
        int total = BATCH * NCHUNK * N4;       // 32768 threads
        scan_ends_kernel<<<total / 256, 256>>>(logA);
        scan_apply_kernel<<<total / 256, 256>>>(logA);
    }

    // GEMM2: y(fp32) = h(fp16) @ C_w^T + C_b
    {
        dim3 grid(D_MODEL / BN, MROWS / BM);   // (4, 128)
        gemm2_a16_o32<<<grid, NTHREADS, SMEM_GEMM_TOTAL>>>(bxh, w2h, C_b, y);
    }
}

// round 15
// speedup vs baseline: 2.8314x; 1.0239x over previous
#include <cuda_runtime.h>
#include <cuda_fp16.h>
#include <math.h>
#include <stdint.h>

// ---------------------------------------------------------------------------
// Problem shape (fixed)
// ---------------------------------------------------------------------------
constexpr int BATCH = 8;
constexpr int SEQ_T = 2048;
constexpr int D_MODEL = 1024;
constexpr int N_STATE = 1024;
constexpr int MROWS = BATCH * SEQ_T;      // 16384
constexpr int KDIM = 1024;
constexpr int CHUNK = 64;
constexpr int NCHUNK = SEQ_T / CHUNK;     // 32

// Scratch (no cudaMalloc allowed)
__device__ __half g_bxh[MROWS * N_STATE];               // B_x (fp16) -> h (fp16), in place
__device__ __half g_w1h[N_STATE * D_MODEL];             // fp16(B_w)
__device__ __half g_w2h[D_MODEL * N_STATE];             // fp16(C_w)
__device__ float  g_end[BATCH * NCHUNK * N_STATE];      // chunk-end states (1 MB)

__device__ __forceinline__ float sigmoidf_(float x) {
    return 1.0f / (1.0f + __expf(-x));
}
__device__ __forceinline__ uint32_t smem_u32(const void* p) {
    uint32_t a;
    asm("{ .reg .u64 t; cvta.to.shared.u64 t, %1; cvt.u32.u64 %0, t; }" : "=r"(a) : "l"(p));
    return a;
}

#define CP_ASYNC16(dst, src) \
    asm volatile("cp.async.cg.shared.global [%0], [%1], 16;" :: "r"(dst), "l"(src))
#define CP_COMMIT() asm volatile("cp.async.commit_group;" ::: "memory")
#define CP_WAIT2()  asm volatile("cp.async.wait_group 2;" ::: "memory")

#define LDSM_X4(r0, r1, r2, r3, addr) \
    asm volatile("ldmatrix.sync.aligned.m8n8.x4.shared.b16 {%0,%1,%2,%3}, [%4];" \
        : "=r"(r0), "=r"(r1), "=r"(r2), "=r"(r3) : "r"(addr))

// ---------------------------------------------------------------------------
// Shared GEMM geometry: CTA tile 128x256x64 fp16, 512 thr / 16 warps,
// warp tile 64x32 (m16n8k16), 4-stage pipeline, SW128 smem.
// ---------------------------------------------------------------------------
constexpr int BM = 128, BN = 256, BK = 64;
constexpr int A_BYTES = BM * 128;                 // 16 KB (64 halves/row = 128B)
constexpr int B_BYTES = BN * 128;                 // 32 KB
constexpr int STAGE_BYTES = A_BYTES + B_BYTES;    // 48 KB
constexpr int NSTAGE = 4;
constexpr int SMEM_GEMM_TOTAL = NSTAGE * STAGE_BYTES;  // 192 KB
constexpr int NITER = KDIM / BK;                  // 16
constexpr int NTHREADS = 512;

// GEMM1: A fp32 (x), B fp16 (w1), OUT fp16 (B_x)
__global__ __launch_bounds__(NTHREADS, 1) void gemm1_a32_o16(
    const float* __restrict__ A, const __half* __restrict__ Bw,
    const float* __restrict__ bias, __half* __restrict__ C)
{
    extern __shared__ char smem[];
    const uint32_t sb = smem_u32(smem);
    const int tid = threadIdx.x;
    const int wid = tid >> 5;
    const int lane = tid & 31;
    const int g = lane >> 2;
    const int t = lane & 3;
    const int mBase = blockIdx.y * BM;
    const int nBase = blockIdx.x * BN;
    const int warpM = (wid & 1) * 64;
    const int warpN = (wid >> 1) * 32;
    const int j = lane >> 3;
    const int r = lane & 7;

    uint32_t aRow[4], aXor[4];
#pragma unroll
    for (int mt = 0; mt < 4; mt++) {
        int row = warpM + mt * 16 + (j & 1) * 8 + r;
        aRow[mt] = (uint32_t)row * 128u;
        aXor[mt] = (uint32_t)(row & 7) << 4;
    }
    const uint32_t aKj = (uint32_t)(j >> 1);
    uint32_t bRow[2], bXor[2];
#pragma unroll
    for (int ntp = 0; ntp < 2; ntp++) {
        int row = warpN + ntp * 16 + (j >> 1) * 8 + r;
        bRow[ntp] = (uint32_t)row * 128u;
        bXor[ntp] = (uint32_t)(row & 7) << 4;
    }
    const uint32_t bKj = (uint32_t)(j & 1);

    float acc[4][4][4];
#pragma unroll
    for (int mt = 0; mt < 4; mt++)
#pragma unroll
        for (int nt = 0; nt < 4; nt++)
#pragma unroll
            for (int q = 0; q < 4; q++) acc[mt][nt][q] = 0.0f;

    uint32_t af[4][4];
    uint32_t bf[4][2];

    // fill: B via cp.async (4 chunks/thread); A via LDG fp32 + cvt + STS fp16
    auto fill = [&](int s, int k0) {
        uint32_t stBase = sb + (uint32_t)s * STAGE_BYTES;
        char* stPtr = smem + (size_t)s * STAGE_BYTES;
#pragma unroll
        for (int q = 0; q < 4; q++) {
            int idx = q * NTHREADS + tid;
            int row = idx >> 3;
            int col = idx & 7;
            uint32_t off = (uint32_t)A_BYTES + (uint32_t)row * 128u +
                           (((uint32_t)col << 4) ^ ((uint32_t)(row & 7) << 4));
            const __half* src = Bw + (size_t)(nBase + row) * KDIM + k0 + col * 8;
            CP_ASYNC16(stBase + off, src);
        }
#pragma unroll
        for (int q = 0; q < 2; q++) {
            int idx = q * NTHREADS + tid;
            int row = idx >> 3;
            int col = idx & 7;
            const float4* src = reinterpret_cast<const float4*>(
                A + (size_t)(mBase + row) * KDIM + k0 + col * 8);
            float4 v0 = src[0];
            float4 v1 = src[1];
            __half2 h0 = __floats2half2_rn(v0.x, v0.y);
            __half2 h1 = __floats2half2_rn(v0.z, v0.w);
            __half2 h2 = __floats2half2_rn(v1.x, v1.y);
            __half2 h3 = __floats2half2_rn(v1.z, v1.w);
            uint4 pk;
            pk.x = *reinterpret_cast<uint32_t*>(&h0);
            pk.y = *reinterpret_cast<uint32_t*>(&h1);
            pk.z = *reinterpret_cast<uint32_t*>(&h2);
            pk.w = *reinterpret_cast<uint32_t*>(&h3);
            uint32_t off = (uint32_t)row * 128u +
                           (((uint32_t)col << 4) ^ ((uint32_t)(row & 7) << 4));
            *reinterpret_cast<uint4*>(stPtr + off) = pk;
        }
    };

    fill(0, 0);        CP_COMMIT();
    fill(1, BK);       CP_COMMIT();
    fill(2, 2 * BK);   CP_COMMIT();

    int sComp = 0, sFill = 3;
    for (int i = 0; i < NITER; i++) {
        CP_WAIT2();
        __syncthreads();

        const uint32_t aBase = sb + (uint32_t)sComp * STAGE_BYTES;
        const uint32_t bBase = aBase + A_BYTES;

        int nk = (i + 3) * BK;
        if (nk < KDIM) fill(sFill, nk);
        CP_COMMIT();

#pragma unroll
        for (int ks = 0; ks < 4; ks++) {
            const uint32_t kc0 = (uint32_t)ks * 2u;
#pragma unroll
            for (int mt = 0; mt < 4; mt++) {
                uint32_t addr = aBase + aRow[mt] + ((((kc0 + aKj) << 4)) ^ aXor[mt]);
                LDSM_X4(af[mt][0], af[mt][1], af[mt][2], af[mt][3], addr);
            }
#pragma unroll
            for (int ntp = 0; ntp < 2; ntp++) {
                uint32_t addr = bBase + bRow[ntp] + ((((kc0 + bKj) << 4)) ^ bXor[ntp]);
                LDSM_X4(bf[2 * ntp][0], bf[2 * ntp][1],
                        bf[2 * ntp + 1][0], bf[2 * ntp + 1][1], addr);
            }
#pragma unroll
            for (int mt = 0; mt < 4; mt++)
#pragma unroll
                for (int nt = 0; nt < 4; nt++) {
                    asm volatile(
                        "mma.sync.aligned.m16n8k16.row.col.f32.f16.f16.f32 "
                        "{%0,%1,%2,%3}, {%4,%5,%6,%7}, {%8,%9}, {%0,%1,%2,%3};"
                        : "+f"(acc[mt][nt][0]), "+f"(acc[mt][nt][1]),
                          "+f"(acc[mt][nt][2]), "+f"(acc[mt][nt][3])
                        : "r"(af[mt][0]), "r"(af[mt][1]),
                          "r"(af[mt][2]), "r"(af[mt][3]),
                          "r"(bf[nt][0]), "r"(bf[nt][1]));
                }
        }
        sComp = (sComp == NSTAGE - 1) ? 0 : sComp + 1;
        sFill = (sFill == NSTAGE - 1) ? 0 : sFill + 1;
    }

#pragma unroll
    for (int mt = 0; mt < 4; mt++) {
        int row0 = mBase + warpM + mt * 16 + g;
#pragma unroll
        for (int nt = 0; nt < 4; nt++) {
            int col = nBase + warpN + nt * 8 + 2 * t;
            float b0 = bias[col], b1 = bias[col + 1];
            __half2 v0 = __floats2half2_rn(acc[mt][nt][0] + b0, acc[mt][nt][1] + b1);
            __half2 v1 = __floats2half2_rn(acc[mt][nt][2] + b0, acc[mt][nt][3] + b1);
            *reinterpret_cast<__half2*>(C + (size_t)row0 * 1024 + col) = v0;
            *reinterpret_cast<__half2*>(C + (size_t)(row0 + 8) * 1024 + col) = v1;
        }
    }
}

// GEMM2: A fp16 (h), B fp16 (w2), OUT fp32 (y)
__global__ __launch_bounds__(NTHREADS, 1) void gemm2_a16_o32(
    const __half* __restrict__ A, const __half* __restrict__ Bw,
    const float* __restrict__ bias, float* __restrict__ C)
{
    extern __shared__ char smem[];
    const uint32_t sb = smem_u32(smem);
    const int tid = threadIdx.x;
    const int wid = tid >> 5;
    const int lane = tid & 31;
    const int g = lane >> 2;
    const int t = lane & 3;
    const int mBase = blockIdx.y * BM;
    const int nBase = blockIdx.x * BN;
    const int warpM = (wid & 1) * 64;
    const int warpN = (wid >> 1) * 32;
    const int j = lane >> 3;
    const int r = lane & 7;

    uint32_t aRow[4], aXor[4];
#pragma unroll
    for (int mt = 0; mt < 4; mt++) {
        int row = warpM + mt * 16 + (j & 1) * 8 + r;
        aRow[mt] = (uint32_t)row * 128u;
        aXor[mt] = (uint32_t)(row & 7) << 4;
    }
    const uint32_t aKj = (uint32_t)(j >> 1);
    uint32_t bRow[2], bXor[2];
#pragma unroll
    for (int ntp = 0; ntp < 2; ntp++) {
        int row = warpN + ntp * 16 + (j >> 1) * 8 + r;
        bRow[ntp] = (uint32_t)row * 128u;
        bXor[ntp] = (uint32_t)(row & 7) << 4;
    }
    const uint32_t bKj = (uint32_t)(j & 1);

    float acc[4][4][4];
#pragma unroll
    for (int mt = 0; mt < 4; mt++)
#pragma unroll
        for (int nt = 0; nt < 4; nt++)
#pragma unroll
            for (int q = 0; q < 4; q++) acc[mt][nt][q] = 0.0f;

    uint32_t af[4][4];
    uint32_t bf[4][2];

    auto fill = [&](int s, int k0) {
        uint32_t stBase = sb + (uint32_t)s * STAGE_BYTES;
#pragma unroll
        for (int q = 0; q < 6; q++) {
            int idx = q * NTHREADS + tid;       // 0..3071
            int row = idx >> 3;                 // 0..383
            int col = idx & 7;
            uint32_t off = (uint32_t)row * 128u +
                           (((uint32_t)col << 4) ^ ((uint32_t)(row & 7) << 4));
            const __half* src = (row < BM)
                ? A  + (size_t)(mBase + row) * KDIM + k0 + col * 8
                : Bw + (size_t)(nBase + row - BM) * KDIM + k0 + col * 8;
            CP_ASYNC16(stBase + off, src);
        }
    };

    fill(0, 0);        CP_COMMIT();
    fill(1, BK);       CP_COMMIT();
    fill(2, 2 * BK);   CP_COMMIT();

    int sComp = 0, sFill = 3;
    for (int i = 0; i < NITER; i++) {
        CP_WAIT2();
        __syncthreads();

        const uint32_t aBase = sb + (uint32_t)sComp * STAGE_BYTES;
        const uint32_t bBase = aBase + A_BYTES;

        int nk = (i + 3) * BK;
        if (nk < KDIM) fill(sFill, nk);
        CP_COMMIT();

#pragma unroll
        for (int ks = 0; ks < 4; ks++) {
            const uint32_t kc0 = (uint32_t)ks * 2u;
#pragma unroll
            for (int mt = 0; mt < 4; mt++) {
                uint32_t addr = aBase + aRow[mt] + ((((kc0 + aKj) << 4)) ^ aXor[mt]);
                LDSM_X4(af[mt][0], af[mt][1], af[mt][2], af[mt][3], addr);
            }
#pragma unroll
            for (int ntp = 0; ntp < 2; ntp++) {
                uint32_t addr = bBase + bRow[ntp] + ((((kc0 + bKj) << 4)) ^ bXor[ntp]);
                LDSM_X4(bf[2 * ntp][0], bf[2 * ntp][1],
                        bf[2 * ntp + 1][0], bf[2 * ntp + 1][1], addr);
            }
#pragma unroll
            for (int mt = 0; mt < 4; mt++)
#pragma unroll
                for (int nt = 0; nt < 4; nt++) {
                    asm volatile(
                        "mma.sync.aligned.m16n8k16.row.col.f32.f16.f16.f32 "
                        "{%0,%1,%2,%3}, {%4,%5,%6,%7}, {%8,%9}, {%0,%1,%2,%3};"
                        : "+f"(acc[mt][nt][0]), "+f"(acc[mt][nt][1]),
                          "+f"(acc[mt][nt][2]), "+f"(acc[mt][nt][3])
                        : "r"(af[mt][0]), "r"(af[mt][1]),
                          "r"(af[mt][2]), "r"(af[mt][3]),
                          "r"(bf[nt][0]), "r"(bf[nt][1]));
                }
        }
        sComp = (sComp == NSTAGE - 1) ? 0 : sComp + 1;
        sFill = (sFill == NSTAGE - 1) ? 0 : sFill + 1;
    }

#pragma unroll
    for (int mt = 0; mt < 4; mt++) {
        int row0 = mBase + warpM + mt * 16 + g;
#pragma unroll
        for (int nt = 0; nt < 4; nt++) {
            int col = nBase + warpN + nt * 8 + 2 * t;
            float b0 = bias[col], b1 = bias[col + 1];
            float2 v0 = make_float2(acc[mt][nt][0] + b0, acc[mt][nt][1] + b1);
            float2 v1 = make_float2(acc[mt][nt][2] + b0, acc[mt][nt][3] + b1);
            *reinterpret_cast<float2*>(C + (size_t)row0 * 1024 + col) = v0;
            *reinterpret_cast<float2*>(C + (size_t)(row0 + 8) * 1024 + col) = v1;
        }
    }
}

// ---------------------------------------------------------------------------
// Fused weight conversion: both B_w and C_w in one launch
// ---------------------------------------------------------------------------
constexpr int W_N4 = N_STATE * D_MODEL / 4;       // 262144 float4 per weight

__global__ __launch_bounds__(256) void conv_w_kernel(
    const float* __restrict__ w1, const float* __restrict__ w2)
{
    int i = blockIdx.x * blockDim.x + threadIdx.x;
    const float* src = (i < W_N4) ? w1 : w2;
    __half* dst = (i < W_N4) ? g_w1h : g_w2h;
    int k = (i < W_N4) ? i : i - W_N4;
    float4 v = reinterpret_cast<const float4*>(src)[k];
    __half2 h01 = __floats2half2_rn(v.x, v.y);
    __half2 h23 = __floats2half2_rn(v.z, v.w);
    uint2 packed;
    packed.x = *reinterpret_cast<uint32_t*>(&h01);
    packed.y = *reinterpret_cast<uint32_t*>(&h23);
    reinterpret_cast<uint2*>(dst)[k] = packed;
}

// ---------------------------------------------------------------------------
// Scan stage 1 (vectorized x4, CHUNK=64): chunk-end states from fp16 B_x
// ---------------------------------------------------------------------------
constexpr int N4 = N_STATE / 4;                   // 256

__global__ __launch_bounds__(256) void scan_ends_kernel(const float* __restrict__ log_A)
{
    int idx = blockIdx.x * blockDim.x + threadIdx.x;   // B*NCHUNK*N4 = 65536
    int n4 = idx & (N4 - 1);
    int c = (idx / N4) & (NCHUNK - 1);
    int b = idx / (N4 * NCHUNK);
    if (b >= BATCH) return;

    float4 la = reinterpret_cast<const float4*>(log_A)[n4];
    float A0 = sigmoidf_(la.x), A1 = sigmoidf_(la.y);
    float A2 = sigmoidf_(la.z), A3 = sigmoidf_(la.w);

    const uint2* src = reinterpret_cast<const uint2*>(
        g_bxh + ((size_t)b * SEQ_T + (size_t)c * CHUNK) * N_STATE) + n4;
    float h0 = 0.f, h1 = 0.f, h2 = 0.f, h3 = 0.f;
#pragma unroll 8
    for (int tt = 0; tt < CHUNK; tt++) {
        uint2 v = src[(size_t)tt * N4];
        __half2 p0 = *reinterpret_cast<__half2*>(&v.x);
        __half2 p1 = *reinterpret_cast<__half2*>(&v.y);
        float2 f0 = __half22float2(p0);
        float2 f1 = __half22float2(p1);
        h0 = fmaf(A0, h0, f0.x);
        h1 = fmaf(A1, h1, f0.y);
        h2 = fmaf(A2, h2, f1.x);
        h3 = fmaf(A3, h3, f1.y);
    }
    float4 e = make_float4(h0, h1, h2, h3);
    reinterpret_cast<float4*>(g_end + ((size_t)b * NCHUNK + c) * N_STATE)[n4] = e;
}

// ---------------------------------------------------------------------------
// Scan stage 2 (vectorized x4, CHUNK=64): carry + inclusive scan, fp16 in place
// ---------------------------------------------------------------------------
__global__ __launch_bounds__(256) void scan_apply_kernel(const float* __restrict__ log_A)
{
    int idx = blockIdx.x * blockDim.x + threadIdx.x;
    int n4 = idx & (N4 - 1);
    int c = (idx / N4) & (NCHUNK - 1);
    int b = idx / (N4 * NCHUNK);
    if (b >= BATCH) return;

    float4 la = reinterpret_cast<const float4*>(log_A)[n4];
    float A0 = sigmoidf_(la.x), A1 = sigmoidf_(la.y);
    float A2 = sigmoidf_(la.z), A3 = sigmoidf_(la.w);

    float aL0 = A0, aL1 = A1, aL2 = A2, aL3 = A3;   // A^64
#pragma unroll
    for (int s = 0; s < 6; s++) {
        aL0 *= aL0; aL1 *= aL1; aL2 *= aL2; aL3 *= aL3;
    }

    float E0 = 0.f, E1 = 0.f, E2 = 0.f, E3 = 0.f;
    for (int cp = 0; cp < c; cp++) {
        float4 e = reinterpret_cast<const float4*>(
            g_end + ((size_t)b * NCHUNK + cp) * N_STATE)[n4];
        E0 = fmaf(aL0, E0, e.x);
        E1 = fmaf(aL1, E1, e.y);
        E2 = fmaf(aL2, E2, e.z);
        E3 = fmaf(aL3, E3, e.w);
    }

    uint2* buf = reinterpret_cast<uint2*>(
        g_bxh + ((size_t)b * SEQ_T + (size_t)c * CHUNK) * N_STATE) + n4;
    float h0 = E0, h1 = E1, h2 = E2, h3 = E3;
#pragma unroll 8
    for (int tt = 0; tt < CHUNK; tt++) {
        uint2 v = buf[(size_t)tt * N4];
        __half2 p0 = *reinterpret_cast<__half2*>(&v.x);
        __half2 p1 = *reinterpret_cast<__half2*>(&v.y);
        float2 f0 = __half22float2(p0);
        float2 f1 = __half22float2(p1);
        h0 = fmaf(A0, h0, f0.x);
        h1 = fmaf(A1, h1, f0.y);
        h2 = fmaf(A2, h2, f1.x);
        h3 = fmaf(A3, h3, f1.y);
        __half2 o0 = __floats2half2_rn(h0, h1);
        __half2 o1 = __floats2half2_rn(h2, h3);
        uint2 ov;
        ov.x = *reinterpret_cast<uint32_t*>(&o0);
        ov.y = *reinterpret_cast<uint32_t*>(&o1);
        buf[(size_t)tt * N4] = ov;
    }
}

// ---------------------------------------------------------------------------
// Launch
// ---------------------------------------------------------------------------
extern "C" void kernel_launch(void* const* d_in, const int* in_sizes, int n_in,
                              void* d_out, int out_size)
{
    const float* x    = (const float*)d_in[0];   // [8, 2048, 1024]
    const float* logA = (const float*)d_in[1];   // [1024]
    const float* B_w  = (const float*)d_in[2];   // [1024, 1024] (N, D)
    const float* B_b  = (const float*)d_in[3];   // [1024]
    const float* C_w  = (const float*)d_in[4];   // [1024, 1024] (D, N)
    const float* C_b  = (const float*)d_in[5];   // [1024]
    float* y = (float*)d_out;                    // [8, 2048, 1024]

    __half *bxh, *w1h, *w2h;
    cudaGetSymbolAddress((void**)&bxh, g_bxh);
    cudaGetSymbolAddress((void**)&w1h, g_w1h);
    cudaGetSymbolAddress((void**)&w2h, g_w2h);

    cudaFuncSetAttribute(gemm1_a32_o16, cudaFuncAttributeMaxDynamicSharedMemorySize,
                         SMEM_GEMM_TOTAL);
    cudaFuncSetAttribute(gemm2_a16_o32, cudaFuncAttributeMaxDynamicSharedMemorySize,
                         SMEM_GEMM_TOTAL);

    // fp16 weights (single fused pass)
    conv_w_kernel<<<2 * W_N4 / 256, 256>>>(B_w, C_w);

    // GEMM1: B_x(fp16) = x(fp32) @ B_w^T + B_b
    {
        dim3 grid(N_STATE / BN, MROWS / BM);   // (4, 128)
        gemm1_a32_o16<<<grid, NTHREADS, SMEM_GEMM_TOTAL>>>(x, w1h, B_b, bxh);
    }

    // Scan (2 vectorized passes, CHUNK=64 -> 256 blocks each)
    {
        int total = BATCH * NCHUNK * N4;       // 65536 threads
        scan_ends_kernel<<<total / 256, 256>>>(logA);
        scan_apply_kernel<<<total / 256, 256>>>(logA);
    }

    // GEMM2: y(fp32) = h(fp16) @ C_w^T + C_b
    {
        dim3 grid(D_MODEL / BN, MROWS / BM);   // (4, 128)
        gemm2_a16_o32<<<grid, NTHREADS, SMEM_GEMM_TOTAL>>>(bxh, w2h, C_b, y);
    }
}